// round 1
// baseline (speedup 1.0000x reference)
#include <cuda_runtime.h>

// S5 SSM scan: y[b,t,d] = sum_n C[d,n] * x[b,t,d,n]
//   x[t] = A_tilde * x[t-1] + B_tilde * u[t]
// Substitution p_n = C_n * x_n:
//   p[t] = a * p[t-1] + cb * u[t],  y[t] = sum_n p[t]
// with a = exp(A_real*dt), cb = C * (1-a)*B/A_real, p_init = C*x0.

#define D_MODEL   256
#define D_STATE   64
#define SEQ_LEN   4096
#define BATCH     32
#define N_PAIRS   (BATCH * D_MODEL)   // 8192 independent (b,d) sequences

#define LANES_PER_PAIR   4
#define STATES_PER_LANE  16           // 4*16 = 64 states
#define PAIRS_PER_BLOCK  56
#define THREADS_PER_BLOCK (PAIRS_PER_BLOCK * LANES_PER_PAIR)  // 224 = 7 warps
#define GRID_BLOCKS ((N_PAIRS + PAIRS_PER_BLOCK - 1) / PAIRS_PER_BLOCK)  // 147
#define T_UNROLL 8

// Scratch (device globals: no allocation allowed in kernel_launch)
__device__ float g_a [D_MODEL * D_STATE];
__device__ float g_cb[D_MODEL * D_STATE];
__device__ float g_p0[D_MODEL * D_STATE];

__global__ void precomp_kernel(const float* __restrict__ log_dt,
                               const float* __restrict__ A_real,
                               const float* __restrict__ B,
                               const float* __restrict__ C,
                               const float* __restrict__ x0)
{
    int idx = blockIdx.x * blockDim.x + threadIdx.x;
    if (idx >= D_MODEL * D_STATE) return;
    int d = idx / D_STATE;
    float dt = expf(log_dt[d]);            // DT_SCALE = 1.0
    float Ar = A_real[idx];
    float a  = expf(Ar * dt);
    float bt = (1.0f - a) * B[idx] / Ar;   // B_tilde
    float c  = C[idx];
    g_a [idx] = a;
    g_cb[idx] = c * bt;
    g_p0[idx] = c * x0[idx];
}

__global__ void __launch_bounds__(THREADS_PER_BLOCK)
scan_kernel(const float* __restrict__ u, float* __restrict__ y)
{
    int tid  = blockIdx.x * THREADS_PER_BLOCK + threadIdx.x;
    int pair = tid / LANES_PER_PAIR;
    int sub  = tid & (LANES_PER_PAIR - 1);

    // Keep all lanes alive for shfl; invalid pairs compute on a clone, no store.
    bool valid = (pair < N_PAIRS);
    if (!valid) pair = N_PAIRS - 1;

    int b = pair / D_MODEL;
    int d = pair - b * D_MODEL;

    // Load this lane's 16 states worth of coefficients (vectorized)
    float a_[STATES_PER_LANE], cb_[STATES_PER_LANE], p_[STATES_PER_LANE];
    int base = d * D_STATE + sub * STATES_PER_LANE;
#pragma unroll
    for (int i = 0; i < STATES_PER_LANE; i += 4) {
        float4 av  = *reinterpret_cast<const float4*>(g_a  + base + i);
        float4 cbv = *reinterpret_cast<const float4*>(g_cb + base + i);
        float4 pv  = *reinterpret_cast<const float4*>(g_p0 + base + i);
        a_[i+0] = av.x;  a_[i+1] = av.y;  a_[i+2] = av.z;  a_[i+3] = av.w;
        cb_[i+0] = cbv.x; cb_[i+1] = cbv.y; cb_[i+2] = cbv.z; cb_[i+3] = cbv.w;
        p_[i+0] = pv.x;  p_[i+1] = pv.y;  p_[i+2] = pv.z;  p_[i+3] = pv.w;
    }

    const float* up = u + (size_t)b * SEQ_LEN * D_MODEL + d;
    float*       yp = y + (size_t)b * SEQ_LEN * D_MODEL + d;

    for (int t0 = 0; t0 < SEQ_LEN; t0 += T_UNROLL) {
        // Prefetch T_UNROLL timesteps of u (broadcast within the 4-lane group,
        // 8 consecutive d per warp -> 1 sector per load slot)
        float uv[T_UNROLL];
#pragma unroll
        for (int j = 0; j < T_UNROLL; j++)
            uv[j] = up[(t0 + j) * D_MODEL];

#pragma unroll
        for (int j = 0; j < T_UNROLL; j++) {
            float uj = uv[j];
            // State update: p = a*p + cb*u  (16 MUL + 16 FMA)
#pragma unroll
            for (int i = 0; i < STATES_PER_LANE; i++)
                p_[i] = fmaf(a_[i], p_[i], cb_[i] * uj);

            // Local tree sum of 16 states (15 FADD, depth 4)
            float q0 = p_[0]  + p_[1];
            float q1 = p_[2]  + p_[3];
            float q2 = p_[4]  + p_[5];
            float q3 = p_[6]  + p_[7];
            float q4 = p_[8]  + p_[9];
            float q5 = p_[10] + p_[11];
            float q6 = p_[12] + p_[13];
            float q7 = p_[14] + p_[15];
            float r0 = q0 + q1;
            float r1 = q2 + q3;
            float r2 = q4 + q5;
            float r3 = q6 + q7;
            float s  = (r0 + r1) + (r2 + r3);

            // Cross-lane reduce within the 4-lane group
            s += __shfl_xor_sync(0xffffffffu, s, 1);
            s += __shfl_xor_sync(0xffffffffu, s, 2);

            // sub==0 lanes of a warp store 8 consecutive d -> coalesced sector
            if (sub == 0 && valid)
                yp[(t0 + j) * D_MODEL] = s;
        }
    }
}

extern "C" void kernel_launch(void* const* d_in, const int* in_sizes, int n_in,
                              void* d_out, int out_size)
{
    // metadata order: u, log_dt, A_real, B, C, x0
    const float* u      = (const float*)d_in[0];
    const float* log_dt = (const float*)d_in[1];
    const float* A_real = (const float*)d_in[2];
    const float* B      = (const float*)d_in[3];
    const float* C      = (const float*)d_in[4];
    const float* x0     = (const float*)d_in[5];
    float* y = (float*)d_out;

    precomp_kernel<<<(D_MODEL * D_STATE + 255) / 256, 256>>>(log_dt, A_real, B, C, x0);
    scan_kernel<<<GRID_BLOCKS, THREADS_PER_BLOCK>>>(u, y);
}

// round 2
// speedup vs baseline: 1.5804x; 1.5804x over previous
#include <cuda_runtime.h>

// S5 SSM scan, q-substitution form:
//   q_n[t] = a_n * q_n[t-1] + u[t]        (1 FMA per state-step)
//   y[t]   = sum_n cb_n * q_n[t]          (dot product, FMAs)
// with a = exp(A_real*dt), cb = C*(1-a)*B/A_real, q0 = (C*x0)/cb (0 if cb==0).
// Packed fp32x2 FFMA throughout.

#define D_MODEL   256
#define D_STATE   64
#define SEQ_LEN   4096
#define BATCH     32
#define N_PAIRS   (BATCH * D_MODEL)       // 8192 independent (b,d) sequences

#define LANES            8                // lanes per pair
#define SPL              8                // states per lane (8*8 = 64)
#define PACKS            (SPL / 2)        // 4 f32x2 packs
#define PAIRS_PER_BLOCK  28
#define TPB              (PAIRS_PER_BLOCK * LANES)   // 224 threads = 7 warps
#define GRID             ((N_PAIRS + PAIRS_PER_BLOCK - 1) / PAIRS_PER_BLOCK) // 293
#define T_UNROLL         8

typedef unsigned long long u64p;

__device__ __forceinline__ u64p pack2(float lo, float hi) {
    u64p r; asm("mov.b64 %0, {%1, %2};" : "=l"(r) : "f"(lo), "f"(hi)); return r;
}
__device__ __forceinline__ void unpack2(u64p v, float& lo, float& hi) {
    asm("mov.b64 {%0, %1}, %2;" : "=f"(lo), "=f"(hi) : "l"(v));
}
__device__ __forceinline__ u64p fma2(u64p a, u64p b, u64p c) {
    u64p d; asm("fma.rn.f32x2 %0, %1, %2, %3;" : "=l"(d) : "l"(a), "l"(b), "l"(c)); return d;
}
__device__ __forceinline__ u64p mul2(u64p a, u64p b) {
    u64p d; asm("mul.rn.f32x2 %0, %1, %2;" : "=l"(d) : "l"(a), "l"(b)); return d;
}

// Scratch (device globals: no allocation allowed in kernel_launch)
__device__ float g_a [D_MODEL * D_STATE];
__device__ float g_cb[D_MODEL * D_STATE];
__device__ float g_q0[D_MODEL * D_STATE];

__global__ void precomp_kernel(const float* __restrict__ log_dt,
                               const float* __restrict__ A_real,
                               const float* __restrict__ B,
                               const float* __restrict__ C,
                               const float* __restrict__ x0)
{
    int idx = blockIdx.x * blockDim.x + threadIdx.x;
    if (idx >= D_MODEL * D_STATE) return;
    int d = idx / D_STATE;
    float dt = expf(log_dt[d]);            // DT_SCALE = 1.0
    float Ar = A_real[idx];
    float a  = expf(Ar * dt);
    float bt = (1.0f - a) * B[idx] / Ar;   // B_tilde
    float c  = C[idx];
    float cb = c * bt;
    float p0 = c * x0[idx];
    g_a [idx] = a;
    g_cb[idx] = cb;
    g_q0[idx] = (cb != 0.0f) ? (p0 / cb) : 0.0f;
}

__global__ void __launch_bounds__(TPB)
scan_kernel(const float* __restrict__ u, float* __restrict__ y)
{
    int tid  = blockIdx.x * TPB + threadIdx.x;
    int pair = tid >> 3;              // /LANES
    int sub  = tid & (LANES - 1);

    // Keep all lanes alive for shfl; invalid pairs compute on a clone, no store.
    bool valid = (pair < N_PAIRS);
    if (!valid) pair = N_PAIRS - 1;

    int b = pair >> 8;                // /D_MODEL
    int d = pair & (D_MODEL - 1);

    // Load this lane's 8 states of coefficients, pack to f32x2
    u64p a2[PACKS], cb2[PACKS], q2[PACKS];
    int base = d * D_STATE + sub * SPL;
#pragma unroll
    for (int i = 0; i < PACKS; i += 2) {
        float4 av  = *reinterpret_cast<const float4*>(g_a  + base + 2 * i);
        float4 cbv = *reinterpret_cast<const float4*>(g_cb + base + 2 * i);
        float4 qv  = *reinterpret_cast<const float4*>(g_q0 + base + 2 * i);
        a2 [i]   = pack2(av.x,  av.y);   a2 [i+1] = pack2(av.z,  av.w);
        cb2[i]   = pack2(cbv.x, cbv.y);  cb2[i+1] = pack2(cbv.z, cbv.w);
        q2 [i]   = pack2(qv.x,  qv.y);   q2 [i+1] = pack2(qv.z,  qv.w);
    }

    const float* up = u + (size_t)b * SEQ_LEN * D_MODEL + d;
    float*       yp = y + (size_t)b * SEQ_LEN * D_MODEL + d;

    for (int t0 = 0; t0 < SEQ_LEN; t0 += T_UNROLL) {
        // Prefetch T_UNROLL timesteps of u (broadcast within the 8-lane group)
        float uv[T_UNROLL];
#pragma unroll
        for (int j = 0; j < T_UNROLL; j++)
            uv[j] = up[(t0 + j) * D_MODEL];

#pragma unroll
        for (int j = 0; j < T_UNROLL; j++) {
            u64p u2 = pack2(uv[j], uv[j]);

            // State update: q = a*q + u   (4 packed FFMA2)
#pragma unroll
            for (int i = 0; i < PACKS; i++)
                q2[i] = fma2(a2[i], q2[i], u2);

            // Dot product y_partial = sum cb*q  (1 MUL2 + 3 FFMA2)
            u64p acc = mul2(cb2[0], q2[0]);
            acc = fma2(cb2[1], q2[1], acc);
            acc = fma2(cb2[2], q2[2], acc);
            acc = fma2(cb2[3], q2[3], acc);
            float lo, hi;
            unpack2(acc, lo, hi);
            float s = lo + hi;

            // Cross-lane reduce within the 8-lane group
            s += __shfl_xor_sync(0xffffffffu, s, 1);
            s += __shfl_xor_sync(0xffffffffu, s, 2);
            s += __shfl_xor_sync(0xffffffffu, s, 4);

            // sub==0 lanes of a warp store 4 consecutive d -> coalesced 16B
            if (sub == 0 && valid)
                yp[(t0 + j) * D_MODEL] = s;
        }
    }
}

extern "C" void kernel_launch(void* const* d_in, const int* in_sizes, int n_in,
                              void* d_out, int out_size)
{
    // metadata order: u, log_dt, A_real, B, C, x0
    const float* u      = (const float*)d_in[0];
    const float* log_dt = (const float*)d_in[1];
    const float* A_real = (const float*)d_in[2];
    const float* B      = (const float*)d_in[3];
    const float* C      = (const float*)d_in[4];
    const float* x0     = (const float*)d_in[5];
    float* y = (float*)d_out;

    precomp_kernel<<<(D_MODEL * D_STATE + 255) / 256, 256>>>(log_dt, A_real, B, C, x0);
    scan_kernel<<<GRID, TPB>>>(u, y);
}

// round 3
// speedup vs baseline: 2.3137x; 1.4640x over previous
#include <cuda_runtime.h>

// S5 SSM scan, q-substitution form:
//   q_n[t] = a_n * q_n[t-1] + u[t]        (1 FMA per state-step)
//   y[t]   = sum_n cb_n * q_n[t]          (dot product)
// a = exp(A_real*dt), cb = C*(1-a)*B/A_real, q0 = (C*x0)/cb (0 if cb==0).
// Packed fp32x2 FFMA; 4 lanes per (b,d) pair, 16 states/lane.
// Structure per 8-step block:
//   phase 0: prefetch next block's u (double buffer)
//   phase 1: recurrence + dot accumulation only (dense, short dep chain)
//   phase 2: 8 independent reduce/shfl/store chains (pipeline at issue rate)

#define D_MODEL   256
#define D_STATE   64
#define SEQ_LEN   4096
#define BATCH     32
#define N_PAIRS   (BATCH * D_MODEL)       // 8192

#define LANES            4
#define SPL              16               // states per lane
#define PACKS            (SPL / 2)        // 8 f32x2 packs
#define PAIRS_PER_BLOCK  56
#define TPB              (PAIRS_PER_BLOCK * LANES)   // 224 = 7 warps
#define GRID             ((N_PAIRS + PAIRS_PER_BLOCK - 1) / PAIRS_PER_BLOCK) // 147
#define T_UNROLL         8

typedef unsigned long long u64p;

__device__ __forceinline__ u64p pack2(float lo, float hi) {
    u64p r; asm("mov.b64 %0, {%1, %2};" : "=l"(r) : "f"(lo), "f"(hi)); return r;
}
__device__ __forceinline__ void unpack2(u64p v, float& lo, float& hi) {
    asm("mov.b64 {%0, %1}, %2;" : "=f"(lo), "=f"(hi) : "l"(v));
}
__device__ __forceinline__ u64p fma2(u64p a, u64p b, u64p c) {
    u64p d; asm("fma.rn.f32x2 %0, %1, %2, %3;" : "=l"(d) : "l"(a), "l"(b), "l"(c)); return d;
}
__device__ __forceinline__ u64p mul2(u64p a, u64p b) {
    u64p d; asm("mul.rn.f32x2 %0, %1, %2;" : "=l"(d) : "l"(a), "l"(b)); return d;
}

// Scratch (device globals: no allocation allowed in kernel_launch)
__device__ float g_a [D_MODEL * D_STATE];
__device__ float g_cb[D_MODEL * D_STATE];
__device__ float g_q0[D_MODEL * D_STATE];

__global__ void precomp_kernel(const float* __restrict__ log_dt,
                               const float* __restrict__ A_real,
                               const float* __restrict__ B,
                               const float* __restrict__ C,
                               const float* __restrict__ x0)
{
    int idx = blockIdx.x * blockDim.x + threadIdx.x;
    if (idx >= D_MODEL * D_STATE) return;
    int d = idx / D_STATE;
    float dt = expf(log_dt[d]);            // DT_SCALE = 1.0
    float Ar = A_real[idx];
    float a  = expf(Ar * dt);
    float bt = (1.0f - a) * B[idx] / Ar;   // B_tilde
    float c  = C[idx];
    float cb = c * bt;
    float p0 = c * x0[idx];
    g_a [idx] = a;
    g_cb[idx] = cb;
    g_q0[idx] = (cb != 0.0f) ? (p0 / cb) : 0.0f;
}

__global__ void __launch_bounds__(TPB)
scan_kernel(const float* __restrict__ u, float* __restrict__ y)
{
    int tid  = blockIdx.x * TPB + threadIdx.x;
    int pair = tid >> 2;              // / LANES
    int sub  = tid & (LANES - 1);

    bool valid = (pair < N_PAIRS);
    if (!valid) pair = N_PAIRS - 1;   // clone work, no store

    int b = pair >> 8;                // / D_MODEL
    int d = pair & (D_MODEL - 1);

    // Coefficients for this lane's 16 states, packed f32x2
    u64p a2[PACKS], cb2[PACKS], q2[PACKS];
    int base = d * D_STATE + sub * SPL;
#pragma unroll
    for (int i = 0; i < PACKS; i += 2) {
        float4 av  = *reinterpret_cast<const float4*>(g_a  + base + 2 * i);
        float4 cbv = *reinterpret_cast<const float4*>(g_cb + base + 2 * i);
        float4 qv  = *reinterpret_cast<const float4*>(g_q0 + base + 2 * i);
        a2 [i]   = pack2(av.x,  av.y);   a2 [i+1] = pack2(av.z,  av.w);
        cb2[i]   = pack2(cbv.x, cbv.y);  cb2[i+1] = pack2(cbv.z, cbv.w);
        q2 [i]   = pack2(qv.x,  qv.y);   q2 [i+1] = pack2(qv.z,  qv.w);
    }

    const float* up = u + (size_t)b * SEQ_LEN * D_MODEL + d;
    float*       yp = y + (size_t)b * SEQ_LEN * D_MODEL + d;

    // Prime the double buffer with block 0
    float uv_cur[T_UNROLL], uv_nxt[T_UNROLL];
#pragma unroll
    for (int j = 0; j < T_UNROLL; j++)
        uv_cur[j] = __ldcs(up + j * D_MODEL);

    for (int t0 = 0; t0 < SEQ_LEN; t0 += T_UNROLL) {
        // Phase 0: prefetch next block (clamped on the last iteration)
        const float* upn = (t0 + 2 * T_UNROLL <= SEQ_LEN)
                         ? up + (t0 + T_UNROLL) * D_MODEL : up;
#pragma unroll
        for (int j = 0; j < T_UNROLL; j++)
            uv_nxt[j] = __ldcs(upn + j * D_MODEL);

        // Phase 1: recurrence + dot accumulation (serial chain = 4-cyc FFMA2)
        u64p acc[T_UNROLL];
#pragma unroll
        for (int j = 0; j < T_UNROLL; j++) {
            u64p u2 = pack2(uv_cur[j], uv_cur[j]);
#pragma unroll
            for (int i = 0; i < PACKS; i++)
                q2[i] = fma2(a2[i], q2[i], u2);
            // two accumulation chains over even/odd packs
            u64p e = mul2(cb2[0], q2[0]);
            u64p o = mul2(cb2[1], q2[1]);
            e = fma2(cb2[2], q2[2], e);
            o = fma2(cb2[3], q2[3], o);
            e = fma2(cb2[4], q2[4], e);
            o = fma2(cb2[5], q2[5], o);
            e = fma2(cb2[6], q2[6], e);
            o = fma2(cb2[7], q2[7], o);
            // combine into one packed acc (defer horizontal work to phase 2)
            acc[j] = fma2(pack2(1.0f, 1.0f), o, e);
        }

        // Phase 2: 8 independent reduce/shfl/store chains
#pragma unroll
        for (int j = 0; j < T_UNROLL; j++) {
            float lo, hi;
            unpack2(acc[j], lo, hi);
            float s = lo + hi;
            s += __shfl_xor_sync(0xffffffffu, s, 1);
            s += __shfl_xor_sync(0xffffffffu, s, 2);
            if (sub == 0 && valid)
                __stcs(yp + (t0 + j) * D_MODEL, s);
        }

        // Rotate double buffer
#pragma unroll
        for (int j = 0; j < T_UNROLL; j++)
            uv_cur[j] = uv_nxt[j];
    }
}

extern "C" void kernel_launch(void* const* d_in, const int* in_sizes, int n_in,
                              void* d_out, int out_size)
{
    // metadata order: u, log_dt, A_real, B, C, x0
    const float* u      = (const float*)d_in[0];
    const float* log_dt = (const float*)d_in[1];
    const float* A_real = (const float*)d_in[2];
    const float* B      = (const float*)d_in[3];
    const float* C      = (const float*)d_in[4];
    const float* x0     = (const float*)d_in[5];
    float* y = (float*)d_out;

    precomp_kernel<<<(D_MODEL * D_STATE + 255) / 256, 256>>>(log_dt, A_real, B, C, x0);
    scan_kernel<<<GRID, TPB>>>(u, y);
}

// round 4
// speedup vs baseline: 2.5695x; 1.1106x over previous
#include <cuda_runtime.h>

// S5 SSM scan, q-substitution + chunked two-pass form.
//   q_n[t] = a_n*q_n[t-1] + u[t],  y[t] = sum_n cb_n*q_n[t]
// Chunking (CH chunks of CLEN): q[c_in] computed via
//   F_c = chunk-local scan from 0;  Qin[c] = a^CLEN * Qin[c-1] + F[c-1]
// Pass1: compute F (recurrence only, chunks 0..CH-2)
// Mid:   chain Qin across chunks
// Pass2: full scan per chunk from Qin (recurrence + dot + reduce + store)

#define D_MODEL   256
#define D_STATE   64
#define SEQ_LEN   4096
#define BATCH     32
#define N_PAIRS   (BATCH * D_MODEL)       // 8192

#define CH        8
#define CLEN      (SEQ_LEN / CH)          // 512

#define LANES     4
#define SPL       16                      // states per lane
#define PACKS     (SPL / 2)               // 8 f32x2 packs
#define TPB       256
#define T_UNROLL  8

typedef unsigned long long u64p;

__device__ __forceinline__ u64p pack2(float lo, float hi) {
    u64p r; asm("mov.b64 %0, {%1, %2};" : "=l"(r) : "f"(lo), "f"(hi)); return r;
}
__device__ __forceinline__ void unpack2(u64p v, float& lo, float& hi) {
    asm("mov.b64 {%0, %1}, %2;" : "=f"(lo), "=f"(hi) : "l"(v));
}
__device__ __forceinline__ u64p fma2(u64p a, u64p b, u64p c) {
    u64p d; asm("fma.rn.f32x2 %0, %1, %2, %3;" : "=l"(d) : "l"(a), "l"(b), "l"(c)); return d;
}
__device__ __forceinline__ u64p mul2(u64p a, u64p b) {
    u64p d; asm("mul.rn.f32x2 %0, %1, %2;" : "=l"(d) : "l"(a), "l"(b)); return d;
}

// Scratch (device globals: no runtime allocation allowed)
__device__ float g_a  [D_MODEL * D_STATE];
__device__ float g_aP [D_MODEL * D_STATE];   // a^CLEN
__device__ float g_cb [D_MODEL * D_STATE];
__device__ float g_q0 [D_MODEL * D_STATE];
__device__ float g_F  [BATCH * CH * D_MODEL * D_STATE];   // chunk-local finals (c=0..CH-2 used)
__device__ float g_Qin[BATCH * CH * D_MODEL * D_STATE];   // chunk initial states

__global__ void precomp_kernel(const float* __restrict__ log_dt,
                               const float* __restrict__ A_real,
                               const float* __restrict__ B,
                               const float* __restrict__ C,
                               const float* __restrict__ x0)
{
    int idx = blockIdx.x * blockDim.x + threadIdx.x;
    if (idx >= D_MODEL * D_STATE) return;
    int d = idx / D_STATE;
    float dt = expf(log_dt[d]);            // DT_SCALE = 1.0
    float Ar = A_real[idx];
    float ad = Ar * dt;
    float a  = expf(ad);
    float bt = (1.0f - a) * B[idx] / Ar;   // B_tilde
    float c  = C[idx];
    float cb = c * bt;
    float p0 = c * x0[idx];
    g_a [idx] = a;
    g_aP[idx] = expf(ad * (float)CLEN);    // a^CLEN
    g_cb[idx] = cb;
    g_q0[idx] = (cb != 0.0f) ? (p0 / cb) : 0.0f;
}

// ---------------- Pass 1: chunk-local finals (recurrence only) --------------
// Tasks: (b, c=0..CH-2, d).  4 lanes per task, 16 states each.
__global__ void __launch_bounds__(TPB)
pass1_kernel(const float* __restrict__ u)
{
    int tid  = blockIdx.x * TPB + threadIdx.x;
    int task = tid >> 2;
    int sub  = tid & (LANES - 1);

    int d  = task & (D_MODEL - 1);
    int bc = task >> 8;
    int c  = bc % (CH - 1);
    int b  = bc / (CH - 1);

    u64p a2[PACKS], q2[PACKS];
    int base = d * D_STATE + sub * SPL;
#pragma unroll
    for (int i = 0; i < PACKS; i += 2) {
        float4 av = *reinterpret_cast<const float4*>(g_a + base + 2 * i);
        a2[i]   = pack2(av.x, av.y);
        a2[i+1] = pack2(av.z, av.w);
        q2[i]   = 0ull;
        q2[i+1] = 0ull;
    }

    const float* up = u + ((size_t)b * SEQ_LEN + (size_t)c * CLEN) * D_MODEL + d;

    float uv_cur[T_UNROLL], uv_nxt[T_UNROLL];
#pragma unroll
    for (int j = 0; j < T_UNROLL; j++)
        uv_cur[j] = __ldcs(up + j * D_MODEL);

    for (int t0 = 0; t0 < CLEN; t0 += T_UNROLL) {
        const float* upn = (t0 + 2 * T_UNROLL <= CLEN)
                         ? up + (t0 + T_UNROLL) * D_MODEL : up;
#pragma unroll
        for (int j = 0; j < T_UNROLL; j++)
            uv_nxt[j] = __ldcs(upn + j * D_MODEL);

#pragma unroll
        for (int j = 0; j < T_UNROLL; j++) {
            u64p u2 = pack2(uv_cur[j], uv_cur[j]);
#pragma unroll
            for (int i = 0; i < PACKS; i++)
                q2[i] = fma2(a2[i], q2[i], u2);
        }
#pragma unroll
        for (int j = 0; j < T_UNROLL; j++)
            uv_cur[j] = uv_nxt[j];
    }

    // Write chunk-final state F[b][c][d][n-range]
    float* Fp = g_F + (((size_t)b * CH + c) * D_MODEL + d) * D_STATE + sub * SPL;
#pragma unroll
    for (int i = 0; i < PACKS; i += 2) {
        float4 v;
        unpack2(q2[i],   v.x, v.y);
        unpack2(q2[i+1], v.z, v.w);
        *reinterpret_cast<float4*>(Fp + 2 * i) = v;
    }
}

// ---------------- Middle: chain Qin across chunks ---------------------------
// Thread per (b, d, n).
__global__ void __launch_bounds__(TPB)
mid_kernel()
{
    int idx = blockIdx.x * TPB + threadIdx.x;   // b*16384 + d*64 + n
    int dn  = idx & (D_MODEL * D_STATE - 1);
    int b   = idx >> 14;

    float aP = g_aP[dn];
    float q  = g_q0[dn];
    size_t stride = (size_t)D_MODEL * D_STATE;
    float* Qp = g_Qin + (size_t)b * CH * stride + dn;
    const float* Fp = g_F + (size_t)b * CH * stride + dn;

    Qp[0] = q;
#pragma unroll
    for (int c = 1; c < CH; c++) {
        q = fmaf(aP, q, Fp[(c - 1) * stride]);
        Qp[c * stride] = q;
    }
}

// ---------------- Pass 2: full scan per chunk -------------------------------
// Tasks: (b, c, d).  4 lanes per task.
__global__ void __launch_bounds__(TPB)
pass2_kernel(const float* __restrict__ u, float* __restrict__ y)
{
    int tid  = blockIdx.x * TPB + threadIdx.x;
    int task = tid >> 2;
    int sub  = tid & (LANES - 1);

    int d  = task & (D_MODEL - 1);
    int bc = task >> 8;
    int c  = bc & (CH - 1);
    int b  = bc >> 3;

    u64p a2[PACKS], cb2[PACKS], q2[PACKS];
    int base = d * D_STATE + sub * SPL;
    const float* Qp = g_Qin + (((size_t)b * CH + c) * D_MODEL + d) * D_STATE + sub * SPL;
#pragma unroll
    for (int i = 0; i < PACKS; i += 2) {
        float4 av  = *reinterpret_cast<const float4*>(g_a  + base + 2 * i);
        float4 cbv = *reinterpret_cast<const float4*>(g_cb + base + 2 * i);
        float4 qv  = *reinterpret_cast<const float4*>(Qp + 2 * i);
        a2 [i]   = pack2(av.x,  av.y);   a2 [i+1] = pack2(av.z,  av.w);
        cb2[i]   = pack2(cbv.x, cbv.y);  cb2[i+1] = pack2(cbv.z, cbv.w);
        q2 [i]   = pack2(qv.x,  qv.y);   q2 [i+1] = pack2(qv.z,  qv.w);
    }

    const float* up = u + ((size_t)b * SEQ_LEN + (size_t)c * CLEN) * D_MODEL + d;
    float*       yp = y + ((size_t)b * SEQ_LEN + (size_t)c * CLEN) * D_MODEL + d;

    float uv_cur[T_UNROLL], uv_nxt[T_UNROLL];
#pragma unroll
    for (int j = 0; j < T_UNROLL; j++)
        uv_cur[j] = __ldcs(up + j * D_MODEL);

    for (int t0 = 0; t0 < CLEN; t0 += T_UNROLL) {
        const float* upn = (t0 + 2 * T_UNROLL <= CLEN)
                         ? up + (t0 + T_UNROLL) * D_MODEL : up;
#pragma unroll
        for (int j = 0; j < T_UNROLL; j++)
            uv_nxt[j] = __ldcs(upn + j * D_MODEL);

        // Recurrence + dot accumulation
        u64p acc[T_UNROLL];
#pragma unroll
        for (int j = 0; j < T_UNROLL; j++) {
            u64p u2 = pack2(uv_cur[j], uv_cur[j]);
#pragma unroll
            for (int i = 0; i < PACKS; i++)
                q2[i] = fma2(a2[i], q2[i], u2);
            u64p e = mul2(cb2[0], q2[0]);
            u64p o = mul2(cb2[1], q2[1]);
            e = fma2(cb2[2], q2[2], e);
            o = fma2(cb2[3], q2[3], o);
            e = fma2(cb2[4], q2[4], e);
            o = fma2(cb2[5], q2[5], o);
            e = fma2(cb2[6], q2[6], e);
            o = fma2(cb2[7], q2[7], o);
            acc[j] = fma2(pack2(1.0f, 1.0f), o, e);
        }

        // Independent reduce/shfl/store chains
#pragma unroll
        for (int j = 0; j < T_UNROLL; j++) {
            float lo, hi;
            unpack2(acc[j], lo, hi);
            float s = lo + hi;
            s += __shfl_xor_sync(0xffffffffu, s, 1);
            s += __shfl_xor_sync(0xffffffffu, s, 2);
            if (sub == 0)
                __stcs(yp + (t0 + j) * D_MODEL, s);
        }

#pragma unroll
        for (int j = 0; j < T_UNROLL; j++)
            uv_cur[j] = uv_nxt[j];
    }
}

extern "C" void kernel_launch(void* const* d_in, const int* in_sizes, int n_in,
                              void* d_out, int out_size)
{
    // metadata order: u, log_dt, A_real, B, C, x0
    const float* u      = (const float*)d_in[0];
    const float* log_dt = (const float*)d_in[1];
    const float* A_real = (const float*)d_in[2];
    const float* B      = (const float*)d_in[3];
    const float* C      = (const float*)d_in[4];
    const float* x0     = (const float*)d_in[5];
    float* y = (float*)d_out;

    precomp_kernel<<<(D_MODEL * D_STATE + 255) / 256, 256>>>(log_dt, A_real, B, C, x0);

    // Pass 1: (CH-1) chunks * 8192 pairs * 4 lanes
    int p1_threads = BATCH * (CH - 1) * D_MODEL * LANES;   // 229376
    pass1_kernel<<<p1_threads / TPB, TPB>>>(u);

    // Middle: one thread per (b, d, n)
    int mid_threads = BATCH * D_MODEL * D_STATE;           // 524288
    mid_kernel<<<mid_threads / TPB, TPB>>>();

    // Pass 2: CH chunks * 8192 pairs * 4 lanes
    int p2_threads = BATCH * CH * D_MODEL * LANES;         // 262144
    pass2_kernel<<<p2_threads / TPB, TPB>>>(u, y);
}

// round 5
// speedup vs baseline: 2.7758x; 1.0803x over previous
#include <cuda_runtime.h>

// S5 SSM scan, q-substitution + chunked two-pass form.
//   q_n[t] = a_n*q_n[t-1] + u[t],  y[t] = sum_n cb_n*q_n[t]
// Pre-update dot:  y[t] = sum_n (cb*a)_n * q_n[t-1] + (sum_n cb_n) * u[t]
// Pass1: chunk-local finals F (recurrence only, chunks 0..CH-2)
// Mid:   chain Qin across chunks
// Pass2: full scan per chunk from Qin

#define D_MODEL   256
#define D_STATE   64
#define SEQ_LEN   4096
#define BATCH     32
#define N_PAIRS   (BATCH * D_MODEL)       // 8192

#define CH        16
#define CLEN      (SEQ_LEN / CH)          // 256

#define LANES     4
#define SPL       16                      // states per lane
#define PACKS     (SPL / 2)               // 8 f32x2 packs
#define TPB       256
#define T_UNROLL  8

typedef unsigned long long u64p;

__device__ __forceinline__ u64p pack2(float lo, float hi) {
    u64p r; asm("mov.b64 %0, {%1, %2};" : "=l"(r) : "f"(lo), "f"(hi)); return r;
}
__device__ __forceinline__ void unpack2(u64p v, float& lo, float& hi) {
    asm("mov.b64 {%0, %1}, %2;" : "=f"(lo), "=f"(hi) : "l"(v));
}
__device__ __forceinline__ u64p fma2(u64p a, u64p b, u64p c) {
    u64p d; asm("fma.rn.f32x2 %0, %1, %2, %3;" : "=l"(d) : "l"(a), "l"(b), "l"(c)); return d;
}
__device__ __forceinline__ u64p mul2(u64p a, u64p b) {
    u64p d; asm("mul.rn.f32x2 %0, %1, %2;" : "=l"(d) : "l"(a), "l"(b)); return d;
}
__device__ __forceinline__ u64p add2(u64p a, u64p b) {
    u64p d; asm("add.rn.f32x2 %0, %1, %2;" : "=l"(d) : "l"(a), "l"(b)); return d;
}

// Scratch (device globals: no runtime allocation allowed)
__device__ float g_a  [D_MODEL * D_STATE];
__device__ float g_aP [D_MODEL * D_STATE];   // a^CLEN
__device__ float g_cb [D_MODEL * D_STATE];
__device__ float g_q0 [D_MODEL * D_STATE];
__device__ float g_F  [BATCH * CH * D_MODEL * D_STATE];
__device__ float g_Qin[BATCH * CH * D_MODEL * D_STATE];

__global__ void precomp_kernel(const float* __restrict__ log_dt,
                               const float* __restrict__ A_real,
                               const float* __restrict__ B,
                               const float* __restrict__ C,
                               const float* __restrict__ x0)
{
    int idx = blockIdx.x * blockDim.x + threadIdx.x;
    if (idx >= D_MODEL * D_STATE) return;
    int d = idx / D_STATE;
    float dt = expf(log_dt[d]);            // DT_SCALE = 1.0
    float Ar = A_real[idx];
    float ad = Ar * dt;
    float a  = expf(ad);
    float bt = (1.0f - a) * B[idx] / Ar;   // B_tilde
    float c  = C[idx];
    float cb = c * bt;
    float p0 = c * x0[idx];
    g_a [idx] = a;
    g_aP[idx] = expf(ad * (float)CLEN);    // a^CLEN
    g_cb[idx] = cb;
    g_q0[idx] = (cb != 0.0f) ? (p0 / cb) : 0.0f;
}

// ---------------- Pass 1: chunk-local finals (recurrence only) --------------
__global__ void __launch_bounds__(TPB)
pass1_kernel(const float* __restrict__ u)
{
    int tid  = blockIdx.x * TPB + threadIdx.x;
    int task = tid >> 2;
    int sub  = tid & (LANES - 1);

    int d  = task & (D_MODEL - 1);
    int bc = task >> 8;
    int c  = bc % (CH - 1);
    int b  = bc / (CH - 1);

    u64p a2[PACKS], q2[PACKS];
    int base = d * D_STATE + sub * SPL;
#pragma unroll
    for (int i = 0; i < PACKS; i += 2) {
        float4 av = *reinterpret_cast<const float4*>(g_a + base + 2 * i);
        a2[i]   = pack2(av.x, av.y);
        a2[i+1] = pack2(av.z, av.w);
        q2[i]   = 0ull;
        q2[i+1] = 0ull;
    }

    const float* up = u + ((size_t)b * SEQ_LEN + (size_t)c * CLEN) * D_MODEL + d;

    float uvA[T_UNROLL], uvB[T_UNROLL];
#pragma unroll
    for (int j = 0; j < T_UNROLL; j++)
        uvA[j] = __ldcs(up + j * D_MODEL);

    // 2x unrolled ping-pong (CLEN/T_UNROLL = 32 blocks, even count)
    for (int t0 = 0; t0 < CLEN; t0 += 2 * T_UNROLL) {
        const float* upn1 = up + (t0 + T_UNROLL) * D_MODEL;
#pragma unroll
        for (int j = 0; j < T_UNROLL; j++)
            uvB[j] = __ldcs(upn1 + j * D_MODEL);
#pragma unroll
        for (int j = 0; j < T_UNROLL; j++) {
            u64p u2 = pack2(uvA[j], uvA[j]);
#pragma unroll
            for (int i = 0; i < PACKS; i++)
                q2[i] = fma2(a2[i], q2[i], u2);
        }
        const float* upn2 = (t0 + 3 * T_UNROLL <= CLEN)
                          ? up + (t0 + 2 * T_UNROLL) * D_MODEL : up;
#pragma unroll
        for (int j = 0; j < T_UNROLL; j++)
            uvA[j] = __ldcs(upn2 + j * D_MODEL);
#pragma unroll
        for (int j = 0; j < T_UNROLL; j++) {
            u64p u2 = pack2(uvB[j], uvB[j]);
#pragma unroll
            for (int i = 0; i < PACKS; i++)
                q2[i] = fma2(a2[i], q2[i], u2);
        }
    }

    float* Fp = g_F + (((size_t)b * CH + c) * D_MODEL + d) * D_STATE + sub * SPL;
#pragma unroll
    for (int i = 0; i < PACKS; i += 2) {
        float4 v;
        unpack2(q2[i],   v.x, v.y);
        unpack2(q2[i+1], v.z, v.w);
        *reinterpret_cast<float4*>(Fp + 2 * i) = v;
    }
}

// ---------------- Middle: chain Qin across chunks ---------------------------
__global__ void __launch_bounds__(TPB)
mid_kernel()
{
    int idx = blockIdx.x * TPB + threadIdx.x;   // b*16384 + d*64 + n
    int dn  = idx & (D_MODEL * D_STATE - 1);
    int b   = idx >> 14;

    float aP = g_aP[dn];
    float q  = g_q0[dn];
    size_t stride = (size_t)D_MODEL * D_STATE;
    float* Qp = g_Qin + (size_t)b * CH * stride + dn;
    const float* Fp = g_F + (size_t)b * CH * stride + dn;

    Qp[0] = q;
#pragma unroll
    for (int c = 1; c < CH; c++) {
        q = fmaf(aP, q, Fp[(c - 1) * stride]);
        Qp[c * stride] = q;
    }
}

// ---------------- Pass 2: full scan per chunk -------------------------------
__global__ void __launch_bounds__(TPB)
pass2_kernel(const float* __restrict__ u, float* __restrict__ y)
{
    int tid  = blockIdx.x * TPB + threadIdx.x;
    int task = tid >> 2;
    int sub  = tid & (LANES - 1);

    int d  = task & (D_MODEL - 1);
    int bc = task >> 8;
    int c  = bc & (CH - 1);
    int b  = bc >> 4;

    u64p a2[PACKS], cba2[PACKS], q2[PACKS];
    float S = 0.0f;                           // sum of this lane's cb
    int base = d * D_STATE + sub * SPL;
    const float* Qp = g_Qin + (((size_t)b * CH + c) * D_MODEL + d) * D_STATE + sub * SPL;
#pragma unroll
    for (int i = 0; i < PACKS; i += 2) {
        float4 av  = *reinterpret_cast<const float4*>(g_a  + base + 2 * i);
        float4 cbv = *reinterpret_cast<const float4*>(g_cb + base + 2 * i);
        float4 qv  = *reinterpret_cast<const float4*>(Qp + 2 * i);
        a2 [i]   = pack2(av.x,  av.y);   a2 [i+1] = pack2(av.z,  av.w);
        cba2[i]   = pack2(cbv.x * av.x, cbv.y * av.y);
        cba2[i+1] = pack2(cbv.z * av.z, cbv.w * av.w);
        S += (cbv.x + cbv.y) + (cbv.z + cbv.w);
        q2 [i]   = pack2(qv.x,  qv.y);   q2 [i+1] = pack2(qv.z,  qv.w);
    }

    const float* up = u + ((size_t)b * SEQ_LEN + (size_t)c * CLEN) * D_MODEL + d;
    float*       yp = y + ((size_t)b * SEQ_LEN + (size_t)c * CLEN) * D_MODEL + d;

    float uvA[T_UNROLL], uvB[T_UNROLL];
#pragma unroll
    for (int j = 0; j < T_UNROLL; j++)
        uvA[j] = __ldcs(up + j * D_MODEL);

    for (int t0 = 0; t0 < CLEN; t0 += 2 * T_UNROLL) {
        // ---- half A ----
        const float* upn1 = up + (t0 + T_UNROLL) * D_MODEL;
#pragma unroll
        for (int j = 0; j < T_UNROLL; j++)
            uvB[j] = __ldcs(upn1 + j * D_MODEL);

        u64p acc[T_UNROLL];
#pragma unroll
        for (int j = 0; j < T_UNROLL; j++) {
            u64p u2 = pack2(uvA[j], uvA[j]);
            // dot on PRE-update q (independent of this step's recurrence)
            u64p e = mul2(cba2[0], q2[0]);
            u64p o = mul2(cba2[1], q2[1]);
            e = fma2(cba2[2], q2[2], e);
            o = fma2(cba2[3], q2[3], o);
            e = fma2(cba2[4], q2[4], e);
            o = fma2(cba2[5], q2[5], o);
            e = fma2(cba2[6], q2[6], e);
            o = fma2(cba2[7], q2[7], o);
#pragma unroll
            for (int i = 0; i < PACKS; i++)
                q2[i] = fma2(a2[i], q2[i], u2);
            acc[j] = add2(e, o);
        }
#pragma unroll
        for (int j = 0; j < T_UNROLL; j++) {
            float lo, hi;
            unpack2(acc[j], lo, hi);
            float s = fmaf(S, uvA[j], lo + hi);
            s += __shfl_xor_sync(0xffffffffu, s, 1);
            s += __shfl_xor_sync(0xffffffffu, s, 2);
            if (sub == 0)
                __stcs(yp + (t0 + j) * D_MODEL, s);
        }

        // ---- half B ----
        const float* upn2 = (t0 + 3 * T_UNROLL <= CLEN)
                          ? up + (t0 + 2 * T_UNROLL) * D_MODEL : up;
#pragma unroll
        for (int j = 0; j < T_UNROLL; j++)
            uvA[j] = __ldcs(upn2 + j * D_MODEL);

#pragma unroll
        for (int j = 0; j < T_UNROLL; j++) {
            u64p u2 = pack2(uvB[j], uvB[j]);
            u64p e = mul2(cba2[0], q2[0]);
            u64p o = mul2(cba2[1], q2[1]);
            e = fma2(cba2[2], q2[2], e);
            o = fma2(cba2[3], q2[3], o);
            e = fma2(cba2[4], q2[4], e);
            o = fma2(cba2[5], q2[5], o);
            e = fma2(cba2[6], q2[6], e);
            o = fma2(cba2[7], q2[7], o);
#pragma unroll
            for (int i = 0; i < PACKS; i++)
                q2[i] = fma2(a2[i], q2[i], u2);
            acc[j] = add2(e, o);
        }
#pragma unroll
        for (int j = 0; j < T_UNROLL; j++) {
            float lo, hi;
            unpack2(acc[j], lo, hi);
            float s = fmaf(S, uvB[j], lo + hi);
            s += __shfl_xor_sync(0xffffffffu, s, 1);
            s += __shfl_xor_sync(0xffffffffu, s, 2);
            if (sub == 0)
                __stcs(yp + (t0 + T_UNROLL + j) * D_MODEL, s);
        }
    }
}

extern "C" void kernel_launch(void* const* d_in, const int* in_sizes, int n_in,
                              void* d_out, int out_size)
{
    // metadata order: u, log_dt, A_real, B, C, x0
    const float* u      = (const float*)d_in[0];
    const float* log_dt = (const float*)d_in[1];
    const float* A_real = (const float*)d_in[2];
    const float* B      = (const float*)d_in[3];
    const float* C      = (const float*)d_in[4];
    const float* x0     = (const float*)d_in[5];
    float* y = (float*)d_out;

    precomp_kernel<<<(D_MODEL * D_STATE + 255) / 256, 256>>>(log_dt, A_real, B, C, x0);

    int p1_threads = BATCH * (CH - 1) * D_MODEL * LANES;   // 491520
    pass1_kernel<<<p1_threads / TPB, TPB>>>(u);

    int mid_threads = BATCH * D_MODEL * D_STATE;           // 524288
    mid_kernel<<<mid_threads / TPB, TPB>>>();

    int p2_threads = BATCH * CH * D_MODEL * LANES;         // 524288
    pass2_kernel<<<p2_threads / TPB, TPB>>>(u, y);
}

// round 6
// speedup vs baseline: 3.0831x; 1.1107x over previous
#include <cuda_runtime.h>

// S5 SSM scan, q-substitution + chunked two-pass form.
//   q_n[t] = a_n*q_n[t-1] + u[t],  y[t] = sum_n cb_n*q_n[t]
// Pre-update dot:  y[t] = sum_n (cb*a)_n * q_n[t-1] + (sum_n cb_n) * u[t]
// Pass1: chunk-local finals F (recurrence only, chunks 0..CH-2)
// Mid:   chain Qin across chunks
// Pass2: full scan per chunk from Qin
// R6: TPB=128 (finer occupancy granularity), scalar acc regs (reg diet).

#define D_MODEL   256
#define D_STATE   64
#define SEQ_LEN   4096
#define BATCH     32
#define N_PAIRS   (BATCH * D_MODEL)       // 8192

#define CH        16
#define CLEN      (SEQ_LEN / CH)          // 256

#define LANES     4
#define SPL       16                      // states per lane
#define PACKS     (SPL / 2)               // 8 f32x2 packs
#define TPB       128
#define T_UNROLL  8

typedef unsigned long long u64p;

__device__ __forceinline__ u64p pack2(float lo, float hi) {
    u64p r; asm("mov.b64 %0, {%1, %2};" : "=l"(r) : "f"(lo), "f"(hi)); return r;
}
__device__ __forceinline__ void unpack2(u64p v, float& lo, float& hi) {
    asm("mov.b64 {%0, %1}, %2;" : "=f"(lo), "=f"(hi) : "l"(v));
}
__device__ __forceinline__ u64p fma2(u64p a, u64p b, u64p c) {
    u64p d; asm("fma.rn.f32x2 %0, %1, %2, %3;" : "=l"(d) : "l"(a), "l"(b), "l"(c)); return d;
}
__device__ __forceinline__ u64p mul2(u64p a, u64p b) {
    u64p d; asm("mul.rn.f32x2 %0, %1, %2;" : "=l"(d) : "l"(a), "l"(b)); return d;
}
__device__ __forceinline__ u64p add2(u64p a, u64p b) {
    u64p d; asm("add.rn.f32x2 %0, %1, %2;" : "=l"(d) : "l"(a), "l"(b)); return d;
}

// Scratch (device globals: no runtime allocation allowed)
__device__ float g_a  [D_MODEL * D_STATE];
__device__ float g_aP [D_MODEL * D_STATE];   // a^CLEN
__device__ float g_cb [D_MODEL * D_STATE];
__device__ float g_q0 [D_MODEL * D_STATE];
__device__ float g_F  [BATCH * CH * D_MODEL * D_STATE];
__device__ float g_Qin[BATCH * CH * D_MODEL * D_STATE];

__global__ void precomp_kernel(const float* __restrict__ log_dt,
                               const float* __restrict__ A_real,
                               const float* __restrict__ B,
                               const float* __restrict__ C,
                               const float* __restrict__ x0)
{
    int idx = blockIdx.x * blockDim.x + threadIdx.x;
    if (idx >= D_MODEL * D_STATE) return;
    int d = idx / D_STATE;
    float dt = expf(log_dt[d]);            // DT_SCALE = 1.0
    float Ar = A_real[idx];
    float ad = Ar * dt;
    float a  = expf(ad);
    float bt = (1.0f - a) * B[idx] / Ar;   // B_tilde
    float c  = C[idx];
    float cb = c * bt;
    float p0 = c * x0[idx];
    g_a [idx] = a;
    g_aP[idx] = expf(ad * (float)CLEN);    // a^CLEN
    g_cb[idx] = cb;
    g_q0[idx] = (cb != 0.0f) ? (p0 / cb) : 0.0f;
}

// ---------------- Pass 1: chunk-local finals (recurrence only) --------------
__global__ void __launch_bounds__(TPB)
pass1_kernel(const float* __restrict__ u)
{
    int tid  = blockIdx.x * TPB + threadIdx.x;
    int task = tid >> 2;
    int sub  = tid & (LANES - 1);

    int d  = task & (D_MODEL - 1);
    int bc = task >> 8;
    int c  = bc % (CH - 1);
    int b  = bc / (CH - 1);

    u64p a2[PACKS], q2[PACKS];
    int base = d * D_STATE + sub * SPL;
#pragma unroll
    for (int i = 0; i < PACKS; i += 2) {
        float4 av = *reinterpret_cast<const float4*>(g_a + base + 2 * i);
        a2[i]   = pack2(av.x, av.y);
        a2[i+1] = pack2(av.z, av.w);
        q2[i]   = 0ull;
        q2[i+1] = 0ull;
    }

    const float* up = u + ((size_t)b * SEQ_LEN + (size_t)c * CLEN) * D_MODEL + d;

    float uvA[T_UNROLL], uvB[T_UNROLL];
#pragma unroll
    for (int j = 0; j < T_UNROLL; j++)
        uvA[j] = __ldcs(up + j * D_MODEL);

    for (int t0 = 0; t0 < CLEN; t0 += 2 * T_UNROLL) {
        const float* upn1 = up + (t0 + T_UNROLL) * D_MODEL;
#pragma unroll
        for (int j = 0; j < T_UNROLL; j++)
            uvB[j] = __ldcs(upn1 + j * D_MODEL);
#pragma unroll
        for (int j = 0; j < T_UNROLL; j++) {
            u64p u2 = pack2(uvA[j], uvA[j]);
#pragma unroll
            for (int i = 0; i < PACKS; i++)
                q2[i] = fma2(a2[i], q2[i], u2);
        }
        const float* upn2 = (t0 + 3 * T_UNROLL <= CLEN)
                          ? up + (t0 + 2 * T_UNROLL) * D_MODEL : up;
#pragma unroll
        for (int j = 0; j < T_UNROLL; j++)
            uvA[j] = __ldcs(upn2 + j * D_MODEL);
#pragma unroll
        for (int j = 0; j < T_UNROLL; j++) {
            u64p u2 = pack2(uvB[j], uvB[j]);
#pragma unroll
            for (int i = 0; i < PACKS; i++)
                q2[i] = fma2(a2[i], q2[i], u2);
        }
    }

    float* Fp = g_F + (((size_t)b * CH + c) * D_MODEL + d) * D_STATE + sub * SPL;
#pragma unroll
    for (int i = 0; i < PACKS; i += 2) {
        float4 v;
        unpack2(q2[i],   v.x, v.y);
        unpack2(q2[i+1], v.z, v.w);
        *reinterpret_cast<float4*>(Fp + 2 * i) = v;
    }
}

// ---------------- Middle: chain Qin across chunks ---------------------------
__global__ void __launch_bounds__(256)
mid_kernel()
{
    int idx = blockIdx.x * 256 + threadIdx.x;   // b*16384 + d*64 + n
    int dn  = idx & (D_MODEL * D_STATE - 1);
    int b   = idx >> 14;

    float aP = g_aP[dn];
    float q  = g_q0[dn];
    size_t stride = (size_t)D_MODEL * D_STATE;
    float* Qp = g_Qin + (size_t)b * CH * stride + dn;
    const float* Fp = g_F + (size_t)b * CH * stride + dn;

    Qp[0] = q;
#pragma unroll
    for (int c = 1; c < CH; c++) {
        q = fmaf(aP, q, Fp[(c - 1) * stride]);
        Qp[c * stride] = q;
    }
}

// ---------------- Pass 2: full scan per chunk -------------------------------
__global__ void __launch_bounds__(TPB)
pass2_kernel(const float* __restrict__ u, float* __restrict__ y)
{
    int tid  = blockIdx.x * TPB + threadIdx.x;
    int task = tid >> 2;
    int sub  = tid & (LANES - 1);

    int d  = task & (D_MODEL - 1);
    int bc = task >> 8;
    int c  = bc & (CH - 1);
    int b  = bc >> 4;

    u64p a2[PACKS], cba2[PACKS], q2[PACKS];
    float S = 0.0f;                           // sum of this lane's cb
    int base = d * D_STATE + sub * SPL;
    const float* Qp = g_Qin + (((size_t)b * CH + c) * D_MODEL + d) * D_STATE + sub * SPL;
#pragma unroll
    for (int i = 0; i < PACKS; i += 2) {
        float4 av  = *reinterpret_cast<const float4*>(g_a  + base + 2 * i);
        float4 cbv = *reinterpret_cast<const float4*>(g_cb + base + 2 * i);
        float4 qv  = *reinterpret_cast<const float4*>(Qp + 2 * i);
        a2 [i]   = pack2(av.x,  av.y);   a2 [i+1] = pack2(av.z,  av.w);
        cba2[i]   = pack2(cbv.x * av.x, cbv.y * av.y);
        cba2[i+1] = pack2(cbv.z * av.z, cbv.w * av.w);
        S += (cbv.x + cbv.y) + (cbv.z + cbv.w);
        q2 [i]   = pack2(qv.x,  qv.y);   q2 [i+1] = pack2(qv.z,  qv.w);
    }

    const float* up = u + ((size_t)b * SEQ_LEN + (size_t)c * CLEN) * D_MODEL + d;
    float*       yp = y + ((size_t)b * SEQ_LEN + (size_t)c * CLEN) * D_MODEL + d;

    float uvA[T_UNROLL], uvB[T_UNROLL];
#pragma unroll
    for (int j = 0; j < T_UNROLL; j++)
        uvA[j] = __ldcs(up + j * D_MODEL);

    for (int t0 = 0; t0 < CLEN; t0 += 2 * T_UNROLL) {
        // ---- half A ----
        const float* upn1 = up + (t0 + T_UNROLL) * D_MODEL;
#pragma unroll
        for (int j = 0; j < T_UNROLL; j++)
            uvB[j] = __ldcs(upn1 + j * D_MODEL);

        float sA[T_UNROLL];                 // scalar partials (reg diet vs u64p acc)
#pragma unroll
        for (int j = 0; j < T_UNROLL; j++) {
            u64p u2 = pack2(uvA[j], uvA[j]);
            // dot on PRE-update q (independent of this step's recurrence)
            u64p e = mul2(cba2[0], q2[0]);
            u64p o = mul2(cba2[1], q2[1]);
            e = fma2(cba2[2], q2[2], e);
            o = fma2(cba2[3], q2[3], o);
            e = fma2(cba2[4], q2[4], e);
            o = fma2(cba2[5], q2[5], o);
            e = fma2(cba2[6], q2[6], e);
            o = fma2(cba2[7], q2[7], o);
#pragma unroll
            for (int i = 0; i < PACKS; i++)
                q2[i] = fma2(a2[i], q2[i], u2);
            u64p t = add2(e, o);
            float lo, hi;
            unpack2(t, lo, hi);
            sA[j] = lo + hi;
        }
#pragma unroll
        for (int j = 0; j < T_UNROLL; j++) {
            float s = fmaf(S, uvA[j], sA[j]);
            s += __shfl_xor_sync(0xffffffffu, s, 1);
            s += __shfl_xor_sync(0xffffffffu, s, 2);
            if (sub == 0)
                __stcs(yp + (t0 + j) * D_MODEL, s);
        }

        // ---- half B ----
        const float* upn2 = (t0 + 3 * T_UNROLL <= CLEN)
                          ? up + (t0 + 2 * T_UNROLL) * D_MODEL : up;
#pragma unroll
        for (int j = 0; j < T_UNROLL; j++)
            uvA[j] = __ldcs(upn2 + j * D_MODEL);

#pragma unroll
        for (int j = 0; j < T_UNROLL; j++) {
            u64p u2 = pack2(uvB[j], uvB[j]);
            u64p e = mul2(cba2[0], q2[0]);
            u64p o = mul2(cba2[1], q2[1]);
            e = fma2(cba2[2], q2[2], e);
            o = fma2(cba2[3], q2[3], o);
            e = fma2(cba2[4], q2[4], e);
            o = fma2(cba2[5], q2[5], o);
            e = fma2(cba2[6], q2[6], e);
            o = fma2(cba2[7], q2[7], o);
#pragma unroll
            for (int i = 0; i < PACKS; i++)
                q2[i] = fma2(a2[i], q2[i], u2);
            u64p t = add2(e, o);
            float lo, hi;
            unpack2(t, lo, hi);
            sA[j] = lo + hi;
        }
#pragma unroll
        for (int j = 0; j < T_UNROLL; j++) {
            float s = fmaf(S, uvB[j], sA[j]);
            s += __shfl_xor_sync(0xffffffffu, s, 1);
            s += __shfl_xor_sync(0xffffffffu, s, 2);
            if (sub == 0)
                __stcs(yp + (t0 + T_UNROLL + j) * D_MODEL, s);
        }
    }
}

extern "C" void kernel_launch(void* const* d_in, const int* in_sizes, int n_in,
                              void* d_out, int out_size)
{
    // metadata order: u, log_dt, A_real, B, C, x0
    const float* u      = (const float*)d_in[0];
    const float* log_dt = (const float*)d_in[1];
    const float* A_real = (const float*)d_in[2];
    const float* B      = (const float*)d_in[3];
    const float* C      = (const float*)d_in[4];
    const float* x0     = (const float*)d_in[5];
    float* y = (float*)d_out;

    precomp_kernel<<<(D_MODEL * D_STATE + 255) / 256, 256>>>(log_dt, A_real, B, C, x0);

    int p1_threads = BATCH * (CH - 1) * D_MODEL * LANES;   // 491520
    pass1_kernel<<<p1_threads / TPB, TPB>>>(u);

    int mid_threads = BATCH * D_MODEL * D_STATE;           // 524288
    mid_kernel<<<mid_threads / 256, 256>>>();

    int p2_threads = BATCH * CH * D_MODEL * LANES;         // 524288
    pass2_kernel<<<p2_threads / TPB, TPB>>>(u, y);
}

// round 7
// speedup vs baseline: 3.5949x; 1.1660x over previous
#include <cuda_runtime.h>

// S5 SSM scan, q-substitution + chunked two-pass form.
//   q_n[t] = a_n*q_n[t-1] + u[t],  y[t] = sum_n (cb*a)_n*q_n[t-1] + (sum cb)*u[t]
// Pass1: chunk-local finals F (recurrence only).  Mid: chain Qin.  Pass2: full scan.
// R7: u staged through SMEM (float4 LDG -> LDS broadcast), batched y stores.

#define D_MODEL   256
#define D_STATE   64
#define SEQ_LEN   4096
#define BATCH     32

#define CH        16
#define CLEN      (SEQ_LEN / CH)          // 256

#define LANES     4
#define SPL       16
#define PACKS     (SPL / 2)               // 8 f32x2 packs
#define TPB       128                     // 32 pairs/block
#define DPB       32                      // d per block
#define TS        64                      // timesteps per smem tile
#define NTILES    (CLEN / TS)             // 4
#define T_UNROLL  8

typedef unsigned long long u64p;

__device__ __forceinline__ u64p pack2(float lo, float hi) {
    u64p r; asm("mov.b64 %0, {%1, %2};" : "=l"(r) : "f"(lo), "f"(hi)); return r;
}
__device__ __forceinline__ void unpack2(u64p v, float& lo, float& hi) {
    asm("mov.b64 {%0, %1}, %2;" : "=f"(lo), "=f"(hi) : "l"(v));
}
__device__ __forceinline__ u64p fma2(u64p a, u64p b, u64p c) {
    u64p d; asm("fma.rn.f32x2 %0, %1, %2, %3;" : "=l"(d) : "l"(a), "l"(b), "l"(c)); return d;
}
__device__ __forceinline__ u64p mul2(u64p a, u64p b) {
    u64p d; asm("mul.rn.f32x2 %0, %1, %2;" : "=l"(d) : "l"(a), "l"(b)); return d;
}
__device__ __forceinline__ u64p add2(u64p a, u64p b) {
    u64p d; asm("add.rn.f32x2 %0, %1, %2;" : "=l"(d) : "l"(a), "l"(b)); return d;
}

__device__ float g_a  [D_MODEL * D_STATE];
__device__ float g_aP [D_MODEL * D_STATE];
__device__ float g_cb [D_MODEL * D_STATE];
__device__ float g_q0 [D_MODEL * D_STATE];
__device__ float g_F  [BATCH * CH * D_MODEL * D_STATE];
__device__ float g_Qin[BATCH * CH * D_MODEL * D_STATE];

__global__ void precomp_kernel(const float* __restrict__ log_dt,
                               const float* __restrict__ A_real,
                               const float* __restrict__ B,
                               const float* __restrict__ C,
                               const float* __restrict__ x0)
{
    int idx = blockIdx.x * blockDim.x + threadIdx.x;
    if (idx >= D_MODEL * D_STATE) return;
    int d = idx / D_STATE;
    float dt = expf(log_dt[d]);
    float Ar = A_real[idx];
    float ad = Ar * dt;
    float a  = expf(ad);
    float bt = (1.0f - a) * B[idx] / Ar;
    float c  = C[idx];
    float cb = c * bt;
    float p0 = c * x0[idx];
    g_a [idx] = a;
    g_aP[idx] = expf(ad * (float)CLEN);
    g_cb[idx] = cb;
    g_q0[idx] = (cb != 0.0f) ? (p0 / cb) : 0.0f;
}

// ---------------- Pass 1: chunk-local finals (recurrence only) --------------
// block = 32 pairs (32 consecutive d) for fixed (b, c).  grid = 32*15*8 = 3840.
__global__ void __launch_bounds__(TPB, 6)
pass1_kernel(const float* __restrict__ u)
{
    __shared__ float tile[2][TS * DPB];

    int tid  = threadIdx.x;
    int pl   = tid >> 2;              // pair-local = d-local (0..31)
    int sub  = tid & (LANES - 1);

    int blk  = blockIdx.x;
    int dblk = blk & 7;
    int bc   = blk >> 3;
    int c    = bc % (CH - 1);
    int b    = bc / (CH - 1);
    int d    = dblk * DPB + pl;

    u64p a2[PACKS], q2[PACKS];
    int base = d * D_STATE + sub * SPL;
#pragma unroll
    for (int i = 0; i < PACKS; i += 2) {
        float4 av = *reinterpret_cast<const float4*>(g_a + base + 2 * i);
        a2[i]   = pack2(av.x, av.y);
        a2[i+1] = pack2(av.z, av.w);
        q2[i]   = 0ull;
        q2[i+1] = 0ull;
    }

    const float* ubase = u + ((size_t)b * SEQ_LEN + (size_t)c * CLEN) * D_MODEL + dblk * DPB;

    // load tile 0
#pragma unroll
    for (int k = 0; k < 4; k++) {
        int s  = tid + k * TPB;                 // 0..511
        int tl = s >> 3, c4 = (s & 7) * 4;
        float4 v = __ldcs(reinterpret_cast<const float4*>(ubase + tl * D_MODEL + c4));
        *reinterpret_cast<float4*>(&tile[0][tl * DPB + c4]) = v;
    }
    __syncthreads();

    for (int ct = 0; ct < NTILES; ct++) {
        int cur = ct & 1;
        bool hasnext = (ct + 1 < NTILES);
        float4 pf[4];
        if (hasnext) {
            const float* src = ubase + (size_t)(ct + 1) * TS * D_MODEL;
#pragma unroll
            for (int k = 0; k < 4; k++) {
                int s  = tid + k * TPB;
                int tl = s >> 3, c4 = (s & 7) * 4;
                pf[k] = __ldcs(reinterpret_cast<const float4*>(src + tl * D_MODEL + c4));
            }
        }

        const float* tp = tile[cur];
        for (int t0 = 0; t0 < TS; t0 += T_UNROLL) {
            float uv[T_UNROLL];
#pragma unroll
            for (int j = 0; j < T_UNROLL; j++)
                uv[j] = tp[(t0 + j) * DPB + pl];
#pragma unroll
            for (int j = 0; j < T_UNROLL; j++) {
                u64p u2 = pack2(uv[j], uv[j]);
#pragma unroll
                for (int i = 0; i < PACKS; i++)
                    q2[i] = fma2(a2[i], q2[i], u2);
            }
        }

        if (hasnext) {
#pragma unroll
            for (int k = 0; k < 4; k++) {
                int s  = tid + k * TPB;
                int tl = s >> 3, c4 = (s & 7) * 4;
                *reinterpret_cast<float4*>(&tile[cur ^ 1][tl * DPB + c4]) = pf[k];
            }
        }
        __syncthreads();
    }

    float* Fp = g_F + (((size_t)b * CH + c) * D_MODEL + d) * D_STATE + sub * SPL;
#pragma unroll
    for (int i = 0; i < PACKS; i += 2) {
        float4 v;
        unpack2(q2[i],   v.x, v.y);
        unpack2(q2[i+1], v.z, v.w);
        *reinterpret_cast<float4*>(Fp + 2 * i) = v;
    }
}

// ---------------- Middle: chain Qin across chunks ---------------------------
__global__ void __launch_bounds__(256)
mid_kernel()
{
    int idx = blockIdx.x * 256 + threadIdx.x;
    int dn  = idx & (D_MODEL * D_STATE - 1);
    int b   = idx >> 14;

    float aP = g_aP[dn];
    float q  = g_q0[dn];
    size_t stride = (size_t)D_MODEL * D_STATE;
    float* Qp = g_Qin + (size_t)b * CH * stride + dn;
    const float* Fp = g_F + (size_t)b * CH * stride + dn;

    Qp[0] = q;
#pragma unroll
    for (int c = 1; c < CH; c++) {
        q = fmaf(aP, q, Fp[(c - 1) * stride]);
        Qp[c * stride] = q;
    }
}

// ---------------- Pass 2: full scan per chunk -------------------------------
// block = 32 pairs (32 consecutive d) for fixed (b, c).  grid = 32*16*8 = 4096.
__global__ void __launch_bounds__(TPB, 6)
pass2_kernel(const float* __restrict__ u, float* __restrict__ y)
{
    __shared__ float tile[2][TS * DPB];

    int tid  = threadIdx.x;
    int pl   = tid >> 2;
    int sub  = tid & (LANES - 1);

    int blk  = blockIdx.x;
    int dblk = blk & 7;
    int bc   = blk >> 3;
    int c    = bc & (CH - 1);
    int b    = bc >> 4;
    int d    = dblk * DPB + pl;

    u64p a2[PACKS], cba2[PACKS], q2[PACKS];
    float S = 0.0f;
    int base = d * D_STATE + sub * SPL;
    const float* Qp = g_Qin + (((size_t)b * CH + c) * D_MODEL + d) * D_STATE + sub * SPL;
#pragma unroll
    for (int i = 0; i < PACKS; i += 2) {
        float4 av  = *reinterpret_cast<const float4*>(g_a  + base + 2 * i);
        float4 cbv = *reinterpret_cast<const float4*>(g_cb + base + 2 * i);
        float4 qv  = *reinterpret_cast<const float4*>(Qp + 2 * i);
        a2 [i]    = pack2(av.x,  av.y);   a2 [i+1]  = pack2(av.z,  av.w);
        cba2[i]   = pack2(cbv.x * av.x, cbv.y * av.y);
        cba2[i+1] = pack2(cbv.z * av.z, cbv.w * av.w);
        S += (cbv.x + cbv.y) + (cbv.z + cbv.w);
        q2 [i]    = pack2(qv.x,  qv.y);   q2 [i+1]  = pack2(qv.z,  qv.w);
    }

    const float* ubase = u + ((size_t)b * SEQ_LEN + (size_t)c * CLEN) * D_MODEL + dblk * DPB;
    float*       yp    = y + ((size_t)b * SEQ_LEN + (size_t)c * CLEN) * D_MODEL + d;

    // load tile 0
#pragma unroll
    for (int k = 0; k < 4; k++) {
        int s  = tid + k * TPB;
        int tl = s >> 3, c4 = (s & 7) * 4;
        float4 v = __ldcs(reinterpret_cast<const float4*>(ubase + tl * D_MODEL + c4));
        *reinterpret_cast<float4*>(&tile[0][tl * DPB + c4]) = v;
    }
    __syncthreads();

    for (int ct = 0; ct < NTILES; ct++) {
        int cur = ct & 1;
        bool hasnext = (ct + 1 < NTILES);
        float4 pf[4];
        if (hasnext) {
            const float* src = ubase + (size_t)(ct + 1) * TS * D_MODEL;
#pragma unroll
            for (int k = 0; k < 4; k++) {
                int s  = tid + k * TPB;
                int tl = s >> 3, c4 = (s & 7) * 4;
                pf[k] = __ldcs(reinterpret_cast<const float4*>(src + tl * D_MODEL + c4));
            }
        }

        const float* tp = tile[cur];
        for (int t0 = 0; t0 < TS; t0 += T_UNROLL) {
            float uv[T_UNROLL];
#pragma unroll
            for (int j = 0; j < T_UNROLL; j++)
                uv[j] = tp[(t0 + j) * DPB + pl];

            float sA[T_UNROLL];
#pragma unroll
            for (int j = 0; j < T_UNROLL; j++) {
                u64p u2 = pack2(uv[j], uv[j]);
                // dot on PRE-update q (independent of this step's update)
                u64p e = mul2(cba2[0], q2[0]);
                u64p o = mul2(cba2[1], q2[1]);
                e = fma2(cba2[2], q2[2], e);
                o = fma2(cba2[3], q2[3], o);
                e = fma2(cba2[4], q2[4], e);
                o = fma2(cba2[5], q2[5], o);
                e = fma2(cba2[6], q2[6], e);
                o = fma2(cba2[7], q2[7], o);
#pragma unroll
                for (int i = 0; i < PACKS; i++)
                    q2[i] = fma2(a2[i], q2[i], u2);
                u64p t = add2(e, o);
                float lo, hi;
                unpack2(t, lo, hi);
                sA[j] = lo + hi;
            }

            // reduce + batched stores: lane `sub` keeps step j==sub (and j==4+sub);
            // one full-warp STG per 4 timesteps (32 lanes = 8 d x 4 t).
            int tg = ct * TS + t0;
            float sv = 0.0f;
#pragma unroll
            for (int j = 0; j < T_UNROLL; j++) {
                float s = fmaf(S, uv[j], sA[j]);
                s += __shfl_xor_sync(0xffffffffu, s, 1);
                s += __shfl_xor_sync(0xffffffffu, s, 2);
                if ((j & 3) == sub) sv = s;
                if (j == 3)
                    __stcs(yp + (tg + sub) * D_MODEL, sv);
                if (j == 7)
                    __stcs(yp + (tg + 4 + sub) * D_MODEL, sv);
            }
        }

        if (hasnext) {
#pragma unroll
            for (int k = 0; k < 4; k++) {
                int s  = tid + k * TPB;
                int tl = s >> 3, c4 = (s & 7) * 4;
                *reinterpret_cast<float4*>(&tile[cur ^ 1][tl * DPB + c4]) = pf[k];
            }
        }
        __syncthreads();
    }
}

extern "C" void kernel_launch(void* const* d_in, const int* in_sizes, int n_in,
                              void* d_out, int out_size)
{
    const float* u      = (const float*)d_in[0];
    const float* log_dt = (const float*)d_in[1];
    const float* A_real = (const float*)d_in[2];
    const float* B      = (const float*)d_in[3];
    const float* C      = (const float*)d_in[4];
    const float* x0     = (const float*)d_in[5];
    float* y = (float*)d_out;

    precomp_kernel<<<(D_MODEL * D_STATE + 255) / 256, 256>>>(log_dt, A_real, B, C, x0);

    int p1_blocks = BATCH * (CH - 1) * (D_MODEL / DPB);    // 3840
    pass1_kernel<<<p1_blocks, TPB>>>(u);

    int mid_threads = BATCH * D_MODEL * D_STATE;           // 524288
    mid_kernel<<<mid_threads / 256, 256>>>();

    int p2_blocks = BATCH * CH * (D_MODEL / DPB);          // 4096
    pass2_kernel<<<p2_blocks, TPB>>>(u, y);
}

// round 8
// speedup vs baseline: 3.6186x; 1.0066x over previous
#include <cuda_runtime.h>
#include <cstdint>

// S5 SSM scan, q-substitution + chunked two-pass form.
//   q_n[t] = a_n*q_n[t-1] + u[t],  y[t] = sum_n (cb*a)_n*q_n[t-1] + (sum cb)*u[t]
// Pass1: chunk-local finals F.  Mid: chain Qin.  Pass2: full scan.
// R8: cp.async tile prefetch (frees regs), higher occupancy caps.

#define D_MODEL   256
#define D_STATE   64
#define SEQ_LEN   4096
#define BATCH     32

#define CH        16
#define CLEN      (SEQ_LEN / CH)          // 256

#define LANES     4
#define SPL       16
#define PACKS     (SPL / 2)               // 8 f32x2 packs
#define TPB       128                     // 32 pairs/block
#define DPB       32                      // d per block
#define TS        64                      // timesteps per smem tile
#define NTILES    (CLEN / TS)             // 4

typedef unsigned long long u64p;

__device__ __forceinline__ u64p pack2(float lo, float hi) {
    u64p r; asm("mov.b64 %0, {%1, %2};" : "=l"(r) : "f"(lo), "f"(hi)); return r;
}
__device__ __forceinline__ void unpack2(u64p v, float& lo, float& hi) {
    asm("mov.b64 {%0, %1}, %2;" : "=f"(lo), "=f"(hi) : "l"(v));
}
__device__ __forceinline__ u64p fma2(u64p a, u64p b, u64p c) {
    u64p d; asm("fma.rn.f32x2 %0, %1, %2, %3;" : "=l"(d) : "l"(a), "l"(b), "l"(c)); return d;
}
__device__ __forceinline__ u64p mul2(u64p a, u64p b) {
    u64p d; asm("mul.rn.f32x2 %0, %1, %2;" : "=l"(d) : "l"(a), "l"(b)); return d;
}
__device__ __forceinline__ u64p add2(u64p a, u64p b) {
    u64p d; asm("add.rn.f32x2 %0, %1, %2;" : "=l"(d) : "l"(a), "l"(b)); return d;
}
__device__ __forceinline__ uint32_t smem_u32(const void* p) {
    return (uint32_t)__cvta_generic_to_shared(p);
}
__device__ __forceinline__ void cp16(uint32_t s, const void* g) {
    asm volatile("cp.async.cg.shared.global [%0], [%1], 16;" :: "r"(s), "l"(g));
}
#define CP_COMMIT() asm volatile("cp.async.commit_group;" ::: "memory")
#define CP_WAIT0()  asm volatile("cp.async.wait_group 0;" ::: "memory")

__device__ float g_a  [D_MODEL * D_STATE];
__device__ float g_aP [D_MODEL * D_STATE];
__device__ float g_cb [D_MODEL * D_STATE];
__device__ float g_q0 [D_MODEL * D_STATE];
__device__ float g_F  [BATCH * CH * D_MODEL * D_STATE];
__device__ float g_Qin[BATCH * CH * D_MODEL * D_STATE];

__global__ void precomp_kernel(const float* __restrict__ log_dt,
                               const float* __restrict__ A_real,
                               const float* __restrict__ B,
                               const float* __restrict__ C,
                               const float* __restrict__ x0)
{
    int idx = blockIdx.x * blockDim.x + threadIdx.x;
    if (idx >= D_MODEL * D_STATE) return;
    int d = idx / D_STATE;
    float dt = expf(log_dt[d]);
    float Ar = A_real[idx];
    float ad = Ar * dt;
    float a  = expf(ad);
    float bt = (1.0f - a) * B[idx] / Ar;
    float c  = C[idx];
    float cb = c * bt;
    float p0 = c * x0[idx];
    g_a [idx] = a;
    g_aP[idx] = expf(ad * (float)CLEN);
    g_cb[idx] = cb;
    g_q0[idx] = (cb != 0.0f) ? (p0 / cb) : 0.0f;
}

// ---------------- Pass 1: chunk-local finals (recurrence only) --------------
__global__ void __launch_bounds__(TPB, 8)
pass1_kernel(const float* __restrict__ u)
{
    __shared__ float tile[2][TS * DPB];

    int tid  = threadIdx.x;
    int pl   = tid >> 2;
    int sub  = tid & (LANES - 1);

    int blk  = blockIdx.x;
    int dblk = blk & 7;
    int bc   = blk >> 3;
    int c    = bc % (CH - 1);
    int b    = bc / (CH - 1);
    int d    = dblk * DPB + pl;

    u64p a2[PACKS], q2[PACKS];
    int base = d * D_STATE + sub * SPL;
#pragma unroll
    for (int i = 0; i < PACKS; i += 2) {
        float4 av = *reinterpret_cast<const float4*>(g_a + base + 2 * i);
        a2[i]   = pack2(av.x, av.y);
        a2[i+1] = pack2(av.z, av.w);
        q2[i]   = 0ull;
        q2[i+1] = 0ull;
    }

    const float* ubase = u + ((size_t)b * SEQ_LEN + (size_t)c * CLEN) * D_MODEL + dblk * DPB;

    // prologue: tile 0 via cp.async
#pragma unroll
    for (int k = 0; k < 4; k++) {
        int s  = tid + k * TPB;
        int tl = s >> 3, c4 = (s & 7) * 4;
        cp16(smem_u32(&tile[0][tl * DPB + c4]), ubase + tl * D_MODEL + c4);
    }
    CP_COMMIT();

    for (int ct = 0; ct < NTILES; ct++) {
        CP_WAIT0();
        __syncthreads();
        if (ct + 1 < NTILES) {
            const float* src = ubase + (size_t)(ct + 1) * TS * D_MODEL;
            float* dst = tile[(ct + 1) & 1];
#pragma unroll
            for (int k = 0; k < 4; k++) {
                int s  = tid + k * TPB;
                int tl = s >> 3, c4 = (s & 7) * 4;
                cp16(smem_u32(&dst[tl * DPB + c4]), src + tl * D_MODEL + c4);
            }
            CP_COMMIT();
        }

        const float* tp = tile[ct & 1];
        for (int t0 = 0; t0 < TS; t0 += 8) {
            float uv[8];
#pragma unroll
            for (int j = 0; j < 8; j++)
                uv[j] = tp[(t0 + j) * DPB + pl];
#pragma unroll
            for (int j = 0; j < 8; j++) {
                u64p u2 = pack2(uv[j], uv[j]);
#pragma unroll
                for (int i = 0; i < PACKS; i++)
                    q2[i] = fma2(a2[i], q2[i], u2);
            }
        }
    }

    float* Fp = g_F + (((size_t)b * CH + c) * D_MODEL + d) * D_STATE + sub * SPL;
#pragma unroll
    for (int i = 0; i < PACKS; i += 2) {
        float4 v;
        unpack2(q2[i],   v.x, v.y);
        unpack2(q2[i+1], v.z, v.w);
        *reinterpret_cast<float4*>(Fp + 2 * i) = v;
    }
}

// ---------------- Middle: chain Qin across chunks ---------------------------
__global__ void __launch_bounds__(256)
mid_kernel()
{
    int idx = blockIdx.x * 256 + threadIdx.x;
    int dn  = idx & (D_MODEL * D_STATE - 1);
    int b   = idx >> 14;

    float aP = g_aP[dn];
    float q  = g_q0[dn];
    size_t stride = (size_t)D_MODEL * D_STATE;
    float* Qp = g_Qin + (size_t)b * CH * stride + dn;
    const float* Fp = g_F + (size_t)b * CH * stride + dn;

    Qp[0] = q;
#pragma unroll
    for (int c = 1; c < CH; c++) {
        q = fmaf(aP, q, Fp[(c - 1) * stride]);
        Qp[c * stride] = q;
    }
}

// ---------------- Pass 2: full scan per chunk -------------------------------
__global__ void __launch_bounds__(TPB, 7)
pass2_kernel(const float* __restrict__ u, float* __restrict__ y)
{
    __shared__ float tile[2][TS * DPB];

    int tid  = threadIdx.x;
    int pl   = tid >> 2;
    int sub  = tid & (LANES - 1);

    int blk  = blockIdx.x;
    int dblk = blk & 7;
    int bc   = blk >> 3;
    int c    = bc & (CH - 1);
    int b    = bc >> 4;
    int d    = dblk * DPB + pl;

    u64p a2[PACKS], cba2[PACKS], q2[PACKS];
    float S = 0.0f;
    int base = d * D_STATE + sub * SPL;
    const float* Qp = g_Qin + (((size_t)b * CH + c) * D_MODEL + d) * D_STATE + sub * SPL;
#pragma unroll
    for (int i = 0; i < PACKS; i += 2) {
        float4 av  = *reinterpret_cast<const float4*>(g_a  + base + 2 * i);
        float4 cbv = *reinterpret_cast<const float4*>(g_cb + base + 2 * i);
        float4 qv  = *reinterpret_cast<const float4*>(Qp + 2 * i);
        a2 [i]    = pack2(av.x,  av.y);   a2 [i+1]  = pack2(av.z,  av.w);
        cba2[i]   = pack2(cbv.x * av.x, cbv.y * av.y);
        cba2[i+1] = pack2(cbv.z * av.z, cbv.w * av.w);
        S += (cbv.x + cbv.y) + (cbv.z + cbv.w);
        q2 [i]    = pack2(qv.x,  qv.y);   q2 [i+1]  = pack2(qv.z,  qv.w);
    }

    const float* ubase = u + ((size_t)b * SEQ_LEN + (size_t)c * CLEN) * D_MODEL + dblk * DPB;
    float*       yp    = y + ((size_t)b * SEQ_LEN + (size_t)c * CLEN) * D_MODEL + d;

    // prologue: tile 0 via cp.async
#pragma unroll
    for (int k = 0; k < 4; k++) {
        int s  = tid + k * TPB;
        int tl = s >> 3, c4 = (s & 7) * 4;
        cp16(smem_u32(&tile[0][tl * DPB + c4]), ubase + tl * D_MODEL + c4);
    }
    CP_COMMIT();

    for (int ct = 0; ct < NTILES; ct++) {
        CP_WAIT0();
        __syncthreads();
        if (ct + 1 < NTILES) {
            const float* src = ubase + (size_t)(ct + 1) * TS * D_MODEL;
            float* dst = tile[(ct + 1) & 1];
#pragma unroll
            for (int k = 0; k < 4; k++) {
                int s  = tid + k * TPB;
                int tl = s >> 3, c4 = (s & 7) * 4;
                cp16(smem_u32(&dst[tl * DPB + c4]), src + tl * D_MODEL + c4);
            }
            CP_COMMIT();
        }

        const float* tp = tile[ct & 1];
        for (int t0 = 0; t0 < TS; t0 += 4) {
            float uv[4];
#pragma unroll
            for (int j = 0; j < 4; j++)
                uv[j] = tp[(t0 + j) * DPB + pl];

            float sA[4];
#pragma unroll
            for (int j = 0; j < 4; j++) {
                u64p u2 = pack2(uv[j], uv[j]);
                // dot on PRE-update q (independent of this step's update)
                u64p e = mul2(cba2[0], q2[0]);
                u64p o = mul2(cba2[1], q2[1]);
                e = fma2(cba2[2], q2[2], e);
                o = fma2(cba2[3], q2[3], o);
                e = fma2(cba2[4], q2[4], e);
                o = fma2(cba2[5], q2[5], o);
                e = fma2(cba2[6], q2[6], e);
                o = fma2(cba2[7], q2[7], o);
#pragma unroll
                for (int i = 0; i < PACKS; i++)
                    q2[i] = fma2(a2[i], q2[i], u2);
                u64p t = add2(e, o);
                float lo, hi;
                unpack2(t, lo, hi);
                sA[j] = fmaf(S, uv[j], lo + hi);
            }

            // reduce + batched store: lane `sub` keeps step j==sub;
            // one full-warp STG per 4 timesteps (32 lanes = 8 d x 4 t).
            int tg = ct * TS + t0;
            float sv = 0.0f;
#pragma unroll
            for (int j = 0; j < 4; j++) {
                float s = sA[j];
                s += __shfl_xor_sync(0xffffffffu, s, 1);
                s += __shfl_xor_sync(0xffffffffu, s, 2);
                if (j == sub) sv = s;
            }
            __stcs(yp + (tg + sub) * D_MODEL, sv);
        }
    }
}

extern "C" void kernel_launch(void* const* d_in, const int* in_sizes, int n_in,
                              void* d_out, int out_size)
{
    const float* u      = (const float*)d_in[0];
    const float* log_dt = (const float*)d_in[1];
    const float* A_real = (const float*)d_in[2];
    const float* B      = (const float*)d_in[3];
    const float* C      = (const float*)d_in[4];
    const float* x0     = (const float*)d_in[5];
    float* y = (float*)d_out;

    precomp_kernel<<<(D_MODEL * D_STATE + 255) / 256, 256>>>(log_dt, A_real, B, C, x0);

    int p1_blocks = BATCH * (CH - 1) * (D_MODEL / DPB);    // 3840
    pass1_kernel<<<p1_blocks, TPB>>>(u);

    int mid_threads = BATCH * D_MODEL * D_STATE;           // 524288
    mid_kernel<<<mid_threads / 256, 256>>>();

    int p2_blocks = BATCH * CH * (D_MODEL / DPB);          // 4096
    pass2_kernel<<<p2_blocks, TPB>>>(u, y);
}

// round 9
// speedup vs baseline: 3.6682x; 1.0137x over previous
#include <cuda_runtime.h>
#include <cstdint>

// S5 SSM scan, q-substitution + chunked two-pass form.
//   q_n[t] = a_n*q_n[t-1] + u[t],  y[t] = sum_n (cb*a)_n*q_n[t-1] + (sum cb)*u[t]
// Pass1: chunk-local finals F.  Mid: chain Qin.  Pass2: full scan.
// R9: software-pipelined LDS (ping-pong uv) + split-butterfly deferred reduce.

#define D_MODEL   256
#define D_STATE   64
#define SEQ_LEN   4096
#define BATCH     32

#define CH        16
#define CLEN      (SEQ_LEN / CH)          // 256

#define LANES     4
#define SPL       16
#define PACKS     (SPL / 2)               // 8 f32x2 packs
#define TPB       128                     // 32 pairs/block
#define DPB       32                      // d per block
#define TS        64                      // timesteps per smem tile
#define NTILES    (CLEN / TS)             // 4

typedef unsigned long long u64p;

__device__ __forceinline__ u64p pack2(float lo, float hi) {
    u64p r; asm("mov.b64 %0, {%1, %2};" : "=l"(r) : "f"(lo), "f"(hi)); return r;
}
__device__ __forceinline__ void unpack2(u64p v, float& lo, float& hi) {
    asm("mov.b64 {%0, %1}, %2;" : "=f"(lo), "=f"(hi) : "l"(v));
}
__device__ __forceinline__ u64p fma2(u64p a, u64p b, u64p c) {
    u64p d; asm("fma.rn.f32x2 %0, %1, %2, %3;" : "=l"(d) : "l"(a), "l"(b), "l"(c)); return d;
}
__device__ __forceinline__ u64p mul2(u64p a, u64p b) {
    u64p d; asm("mul.rn.f32x2 %0, %1, %2;" : "=l"(d) : "l"(a), "l"(b)); return d;
}
__device__ __forceinline__ u64p add2(u64p a, u64p b) {
    u64p d; asm("add.rn.f32x2 %0, %1, %2;" : "=l"(d) : "l"(a), "l"(b)); return d;
}
__device__ __forceinline__ uint32_t smem_u32(const void* p) {
    return (uint32_t)__cvta_generic_to_shared(p);
}
__device__ __forceinline__ void cp16(uint32_t s, const void* g) {
    asm volatile("cp.async.cg.shared.global [%0], [%1], 16;" :: "r"(s), "l"(g));
}
#define CP_COMMIT() asm volatile("cp.async.commit_group;" ::: "memory")
#define CP_WAIT0()  asm volatile("cp.async.wait_group 0;" ::: "memory")

__device__ float g_a  [D_MODEL * D_STATE];
__device__ float g_aP [D_MODEL * D_STATE];
__device__ float g_cb [D_MODEL * D_STATE];
__device__ float g_q0 [D_MODEL * D_STATE];
__device__ float g_F  [BATCH * CH * D_MODEL * D_STATE];
__device__ float g_Qin[BATCH * CH * D_MODEL * D_STATE];

__global__ void precomp_kernel(const float* __restrict__ log_dt,
                               const float* __restrict__ A_real,
                               const float* __restrict__ B,
                               const float* __restrict__ C,
                               const float* __restrict__ x0)
{
    int idx = blockIdx.x * blockDim.x + threadIdx.x;
    if (idx >= D_MODEL * D_STATE) return;
    int d = idx / D_STATE;
    float dt = expf(log_dt[d]);
    float Ar = A_real[idx];
    float ad = Ar * dt;
    float a  = expf(ad);
    float bt = (1.0f - a) * B[idx] / Ar;
    float c  = C[idx];
    float cb = c * bt;
    float p0 = c * x0[idx];
    g_a [idx] = a;
    g_aP[idx] = expf(ad * (float)CLEN);
    g_cb[idx] = cb;
    g_q0[idx] = (cb != 0.0f) ? (p0 / cb) : 0.0f;
}

// ---------------- Pass 1: chunk-local finals (recurrence only) --------------
__global__ void __launch_bounds__(TPB, 8)
pass1_kernel(const float* __restrict__ u)
{
    __shared__ float tile[2][TS * DPB];

    int tid  = threadIdx.x;
    int pl   = tid >> 2;
    int sub  = tid & (LANES - 1);

    int blk  = blockIdx.x;
    int dblk = blk & 7;
    int bc   = blk >> 3;
    int c    = bc % (CH - 1);
    int b    = bc / (CH - 1);
    int d    = dblk * DPB + pl;

    u64p a2[PACKS], q2[PACKS];
    int base = d * D_STATE + sub * SPL;
#pragma unroll
    for (int i = 0; i < PACKS; i += 2) {
        float4 av = *reinterpret_cast<const float4*>(g_a + base + 2 * i);
        a2[i]   = pack2(av.x, av.y);
        a2[i+1] = pack2(av.z, av.w);
        q2[i]   = 0ull;
        q2[i+1] = 0ull;
    }

    const float* ubase = u + ((size_t)b * SEQ_LEN + (size_t)c * CLEN) * D_MODEL + dblk * DPB;

#pragma unroll
    for (int k = 0; k < 4; k++) {
        int s  = tid + k * TPB;
        int tl = s >> 3, c4 = (s & 7) * 4;
        cp16(smem_u32(&tile[0][tl * DPB + c4]), ubase + tl * D_MODEL + c4);
    }
    CP_COMMIT();

    for (int ct = 0; ct < NTILES; ct++) {
        CP_WAIT0();
        __syncthreads();
        if (ct + 1 < NTILES) {
            const float* src = ubase + (size_t)(ct + 1) * TS * D_MODEL;
            float* dst = tile[(ct + 1) & 1];
#pragma unroll
            for (int k = 0; k < 4; k++) {
                int s  = tid + k * TPB;
                int tl = s >> 3, c4 = (s & 7) * 4;
                cp16(smem_u32(&dst[tl * DPB + c4]), src + tl * D_MODEL + c4);
            }
            CP_COMMIT();
        }

        const float* tp = tile[ct & 1];
        // LDS software pipeline: ping-pong uv groups of 8
        float uv[2][8];
#pragma unroll
        for (int j = 0; j < 8; j++)
            uv[0][j] = tp[j * DPB + pl];

#pragma unroll
        for (int g = 0; g < TS / 8; g++) {
            int t0 = g * 8;
            float* uvC = uv[g & 1];
            float* uvN = uv[(g + 1) & 1];
            if (g + 1 < TS / 8) {
#pragma unroll
                for (int j = 0; j < 8; j++)
                    uvN[j] = tp[(t0 + 8 + j) * DPB + pl];
            }
#pragma unroll
            for (int j = 0; j < 8; j++) {
                u64p u2 = pack2(uvC[j], uvC[j]);
#pragma unroll
                for (int i = 0; i < PACKS; i++)
                    q2[i] = fma2(a2[i], q2[i], u2);
            }
        }
    }

    float* Fp = g_F + (((size_t)b * CH + c) * D_MODEL + d) * D_STATE + sub * SPL;
#pragma unroll
    for (int i = 0; i < PACKS; i += 2) {
        float4 v;
        unpack2(q2[i],   v.x, v.y);
        unpack2(q2[i+1], v.z, v.w);
        *reinterpret_cast<float4*>(Fp + 2 * i) = v;
    }
}

// ---------------- Middle: chain Qin across chunks ---------------------------
__global__ void __launch_bounds__(256)
mid_kernel()
{
    int idx = blockIdx.x * 256 + threadIdx.x;
    int dn  = idx & (D_MODEL * D_STATE - 1);
    int b   = idx >> 14;

    float aP = g_aP[dn];
    float q  = g_q0[dn];
    size_t stride = (size_t)D_MODEL * D_STATE;
    float* Qp = g_Qin + (size_t)b * CH * stride + dn;
    const float* Fp = g_F + (size_t)b * CH * stride + dn;

    Qp[0] = q;
#pragma unroll
    for (int c = 1; c < CH; c++) {
        q = fmaf(aP, q, Fp[(c - 1) * stride]);
        Qp[c * stride] = q;
    }
}

// ---------------- Pass 2: full scan per chunk -------------------------------
__global__ void __launch_bounds__(TPB, 7)
pass2_kernel(const float* __restrict__ u, float* __restrict__ y)
{
    __shared__ float tile[2][TS * DPB];

    int tid  = threadIdx.x;
    int pl   = tid >> 2;
    int sub  = tid & (LANES - 1);

    int blk  = blockIdx.x;
    int dblk = blk & 7;
    int bc   = blk >> 3;
    int c    = bc & (CH - 1);
    int b    = bc >> 4;
    int d    = dblk * DPB + pl;

    u64p a2[PACKS], cba2[PACKS], q2[PACKS];
    float S = 0.0f;
    int base = d * D_STATE + sub * SPL;
    const float* Qp = g_Qin + (((size_t)b * CH + c) * D_MODEL + d) * D_STATE + sub * SPL;
#pragma unroll
    for (int i = 0; i < PACKS; i += 2) {
        float4 av  = *reinterpret_cast<const float4*>(g_a  + base + 2 * i);
        float4 cbv = *reinterpret_cast<const float4*>(g_cb + base + 2 * i);
        float4 qv  = *reinterpret_cast<const float4*>(Qp + 2 * i);
        a2 [i]    = pack2(av.x,  av.y);   a2 [i+1]  = pack2(av.z,  av.w);
        cba2[i]   = pack2(cbv.x * av.x, cbv.y * av.y);
        cba2[i+1] = pack2(cbv.z * av.z, cbv.w * av.w);
        S += (cbv.x + cbv.y) + (cbv.z + cbv.w);
        q2 [i]    = pack2(qv.x,  qv.y);   q2 [i+1]  = pack2(qv.z,  qv.w);
    }

    const float* ubase = u + ((size_t)b * SEQ_LEN + (size_t)c * CLEN) * D_MODEL + dblk * DPB;
    float*       yp    = y + ((size_t)b * SEQ_LEN + (size_t)c * CLEN) * D_MODEL + d;

#pragma unroll
    for (int k = 0; k < 4; k++) {
        int s  = tid + k * TPB;
        int tl = s >> 3, c4 = (s & 7) * 4;
        cp16(smem_u32(&tile[0][tl * DPB + c4]), ubase + tl * D_MODEL + c4);
    }
    CP_COMMIT();

    for (int ct = 0; ct < NTILES; ct++) {
        CP_WAIT0();
        __syncthreads();
        if (ct + 1 < NTILES) {
            const float* src = ubase + (size_t)(ct + 1) * TS * D_MODEL;
            float* dst = tile[(ct + 1) & 1];
#pragma unroll
            for (int k = 0; k < 4; k++) {
                int s  = tid + k * TPB;
                int tl = s >> 3, c4 = (s & 7) * 4;
                cp16(smem_u32(&dst[tl * DPB + c4]), src + tl * D_MODEL + c4);
            }
            CP_COMMIT();
        }

        const float* tp = tile[ct & 1];
        float uv[2][4];
        float t1[4];
        float sA[4];

        // prologue: LDS group 0
#pragma unroll
        for (int j = 0; j < 4; j++)
            uv[0][j] = tp[j * DPB + pl];

#pragma unroll
        for (int g = 0; g < TS / 4; g++) {
            int t0 = g * 4;
            float* uvC = uv[g & 1];
            float* uvN = uv[(g + 1) & 1];

            // (a) LDS next group (latency hidden by this group's compute)
            if (g + 1 < TS / 4) {
#pragma unroll
                for (int j = 0; j < 4; j++)
                    uvN[j] = tp[(t0 + 4 + j) * DPB + pl];
            }

            // (b) compute steps 0,1
#pragma unroll
            for (int j = 0; j < 2; j++) {
                u64p u2 = pack2(uvC[j], uvC[j]);
                u64p e = mul2(cba2[0], q2[0]);
                u64p o = mul2(cba2[1], q2[1]);
                e = fma2(cba2[2], q2[2], e);
                o = fma2(cba2[3], q2[3], o);
                e = fma2(cba2[4], q2[4], e);
                o = fma2(cba2[5], q2[5], o);
                e = fma2(cba2[6], q2[6], e);
                o = fma2(cba2[7], q2[7], o);
#pragma unroll
                for (int i = 0; i < PACKS; i++)
                    q2[i] = fma2(a2[i], q2[i], u2);
                u64p t = add2(e, o);
                float lo, hi;
                unpack2(t, lo, hi);
                sA[j] = fmaf(S, uvC[j], lo + hi);
            }

            // (c) stage-2 reduce + store for group g-1 (t1 from last iteration)
            if (g > 0) {
                float sv = 0.0f;
#pragma unroll
                for (int j = 0; j < 4; j++) {
                    float s = t1[j] + __shfl_xor_sync(0xffffffffu, t1[j], 2);
                    if (j == sub) sv = s;
                }
                __stcs(yp + (ct * TS + t0 - 4 + sub) * D_MODEL, sv);
            }

            // (d) compute steps 2,3
#pragma unroll
            for (int j = 2; j < 4; j++) {
                u64p u2 = pack2(uvC[j], uvC[j]);
                u64p e = mul2(cba2[0], q2[0]);
                u64p o = mul2(cba2[1], q2[1]);
                e = fma2(cba2[2], q2[2], e);
                o = fma2(cba2[3], q2[3], o);
                e = fma2(cba2[4], q2[4], e);
                o = fma2(cba2[5], q2[5], o);
                e = fma2(cba2[6], q2[6], e);
                o = fma2(cba2[7], q2[7], o);
#pragma unroll
                for (int i = 0; i < PACKS; i++)
                    q2[i] = fma2(a2[i], q2[i], u2);
                u64p t = add2(e, o);
                float lo, hi;
                unpack2(t, lo, hi);
                sA[j] = fmaf(S, uvC[j], lo + hi);
            }

            // (e) stage-1 reduce of this group (latency hidden by next iteration)
#pragma unroll
            for (int j = 0; j < 4; j++)
                t1[j] = sA[j] + __shfl_xor_sync(0xffffffffu, sA[j], 1);
        }

        // tile epilogue: stage-2 + store for the last group
        {
            float sv = 0.0f;
#pragma unroll
            for (int j = 0; j < 4; j++) {
                float s = t1[j] + __shfl_xor_sync(0xffffffffu, t1[j], 2);
                if (j == sub) sv = s;
            }
            __stcs(yp + (ct * TS + TS - 4 + sub) * D_MODEL, sv);
        }
    }
}

extern "C" void kernel_launch(void* const* d_in, const int* in_sizes, int n_in,
                              void* d_out, int out_size)
{
    const float* u      = (const float*)d_in[0];
    const float* log_dt = (const float*)d_in[1];
    const float* A_real = (const float*)d_in[2];
    const float* B      = (const float*)d_in[3];
    const float* C      = (const float*)d_in[4];
    const float* x0     = (const float*)d_in[5];
    float* y = (float*)d_out;

    precomp_kernel<<<(D_MODEL * D_STATE + 255) / 256, 256>>>(log_dt, A_real, B, C, x0);

    int p1_blocks = BATCH * (CH - 1) * (D_MODEL / DPB);    // 3840
    pass1_kernel<<<p1_blocks, TPB>>>(u);

    int mid_threads = BATCH * D_MODEL * D_STATE;           // 524288
    mid_kernel<<<mid_threads / 256, 256>>>();

    int p2_blocks = BATCH * CH * (D_MODEL / DPB);          // 4096
    pass2_kernel<<<p2_blocks, TPB>>>(u, y);
}

// round 10
// speedup vs baseline: 3.7080x; 1.0108x over previous
#include <cuda_runtime.h>
#include <cstdint>

// S5 SSM scan, q-substitution + chunked two-pass form.
//   q_n[t] = a_n*q_n[t-1] + u[t],  y[t] = sum_n (cb*a)_n*q_n[t-1] + (sum cb)*u[t]
// Pass1: chunk-local finals F.  Mid: chain Qin.  Pass2: full scan.
// R10: minimal-shuffle quad reduce (3 SHFL per 4 steps instead of 8) via
// select-based send indices; stage-2 still deferred into next group's compute.

#define D_MODEL   256
#define D_STATE   64
#define SEQ_LEN   4096
#define BATCH     32

#define CH        16
#define CLEN      (SEQ_LEN / CH)          // 256

#define LANES     4
#define SPL       16
#define PACKS     (SPL / 2)               // 8 f32x2 packs
#define TPB       128                     // 32 pairs/block
#define DPB       32                      // d per block
#define TS        64                      // timesteps per smem tile
#define NTILES    (CLEN / TS)             // 4

typedef unsigned long long u64p;

__device__ __forceinline__ u64p pack2(float lo, float hi) {
    u64p r; asm("mov.b64 %0, {%1, %2};" : "=l"(r) : "f"(lo), "f"(hi)); return r;
}
__device__ __forceinline__ void unpack2(u64p v, float& lo, float& hi) {
    asm("mov.b64 {%0, %1}, %2;" : "=f"(lo), "=f"(hi) : "l"(v));
}
__device__ __forceinline__ u64p fma2(u64p a, u64p b, u64p c) {
    u64p d; asm("fma.rn.f32x2 %0, %1, %2, %3;" : "=l"(d) : "l"(a), "l"(b), "l"(c)); return d;
}
__device__ __forceinline__ u64p mul2(u64p a, u64p b) {
    u64p d; asm("mul.rn.f32x2 %0, %1, %2;" : "=l"(d) : "l"(a), "l"(b)); return d;
}
__device__ __forceinline__ u64p add2(u64p a, u64p b) {
    u64p d; asm("add.rn.f32x2 %0, %1, %2;" : "=l"(d) : "l"(a), "l"(b)); return d;
}
__device__ __forceinline__ uint32_t smem_u32(const void* p) {
    return (uint32_t)__cvta_generic_to_shared(p);
}
__device__ __forceinline__ void cp16(uint32_t s, const void* g) {
    asm volatile("cp.async.cg.shared.global [%0], [%1], 16;" :: "r"(s), "l"(g));
}
#define CP_COMMIT() asm volatile("cp.async.commit_group;" ::: "memory")
#define CP_WAIT0()  asm volatile("cp.async.wait_group 0;" ::: "memory")

// 4-way select (3 SELs on the ALU pipe; keeps arrays in registers)
__device__ __forceinline__ float sel4(float a0, float a1, float a2, float a3, int idx) {
    float x = (idx & 1) ? a1 : a0;
    float y = (idx & 1) ? a3 : a2;
    return (idx & 2) ? y : x;
}

__device__ float g_a  [D_MODEL * D_STATE];
__device__ float g_aP [D_MODEL * D_STATE];
__device__ float g_cb [D_MODEL * D_STATE];
__device__ float g_q0 [D_MODEL * D_STATE];
__device__ float g_F  [BATCH * CH * D_MODEL * D_STATE];
__device__ float g_Qin[BATCH * CH * D_MODEL * D_STATE];

__global__ void precomp_kernel(const float* __restrict__ log_dt,
                               const float* __restrict__ A_real,
                               const float* __restrict__ B,
                               const float* __restrict__ C,
                               const float* __restrict__ x0)
{
    int idx = blockIdx.x * blockDim.x + threadIdx.x;
    if (idx >= D_MODEL * D_STATE) return;
    int d = idx / D_STATE;
    float dt = expf(log_dt[d]);
    float Ar = A_real[idx];
    float ad = Ar * dt;
    float a  = expf(ad);
    float bt = (1.0f - a) * B[idx] / Ar;
    float c  = C[idx];
    float cb = c * bt;
    float p0 = c * x0[idx];
    g_a [idx] = a;
    g_aP[idx] = expf(ad * (float)CLEN);
    g_cb[idx] = cb;
    g_q0[idx] = (cb != 0.0f) ? (p0 / cb) : 0.0f;
}

// ---------------- Pass 1: chunk-local finals (recurrence only) --------------
__global__ void __launch_bounds__(TPB, 8)
pass1_kernel(const float* __restrict__ u)
{
    __shared__ float tile[2][TS * DPB];

    int tid  = threadIdx.x;
    int pl   = tid >> 2;
    int sub  = tid & (LANES - 1);

    int blk  = blockIdx.x;
    int dblk = blk & 7;
    int bc   = blk >> 3;
    int c    = bc % (CH - 1);
    int b    = bc / (CH - 1);
    int d    = dblk * DPB + pl;

    u64p a2[PACKS], q2[PACKS];
    int base = d * D_STATE + sub * SPL;
#pragma unroll
    for (int i = 0; i < PACKS; i += 2) {
        float4 av = *reinterpret_cast<const float4*>(g_a + base + 2 * i);
        a2[i]   = pack2(av.x, av.y);
        a2[i+1] = pack2(av.z, av.w);
        q2[i]   = 0ull;
        q2[i+1] = 0ull;
    }

    const float* ubase = u + ((size_t)b * SEQ_LEN + (size_t)c * CLEN) * D_MODEL + dblk * DPB;

#pragma unroll
    for (int k = 0; k < 4; k++) {
        int s  = tid + k * TPB;
        int tl = s >> 3, c4 = (s & 7) * 4;
        cp16(smem_u32(&tile[0][tl * DPB + c4]), ubase + tl * D_MODEL + c4);
    }
    CP_COMMIT();

    for (int ct = 0; ct < NTILES; ct++) {
        CP_WAIT0();
        __syncthreads();
        if (ct + 1 < NTILES) {
            const float* src = ubase + (size_t)(ct + 1) * TS * D_MODEL;
            float* dst = tile[(ct + 1) & 1];
#pragma unroll
            for (int k = 0; k < 4; k++) {
                int s  = tid + k * TPB;
                int tl = s >> 3, c4 = (s & 7) * 4;
                cp16(smem_u32(&dst[tl * DPB + c4]), src + tl * D_MODEL + c4);
            }
            CP_COMMIT();
        }

        const float* tp = tile[ct & 1];
        float uv[2][8];
#pragma unroll
        for (int j = 0; j < 8; j++)
            uv[0][j] = tp[j * DPB + pl];

#pragma unroll
        for (int g = 0; g < TS / 8; g++) {
            int t0 = g * 8;
            float* uvC = uv[g & 1];
            float* uvN = uv[(g + 1) & 1];
            if (g + 1 < TS / 8) {
#pragma unroll
                for (int j = 0; j < 8; j++)
                    uvN[j] = tp[(t0 + 8 + j) * DPB + pl];
            }
#pragma unroll
            for (int j = 0; j < 8; j++) {
                u64p u2 = pack2(uvC[j], uvC[j]);
#pragma unroll
                for (int i = 0; i < PACKS; i++)
                    q2[i] = fma2(a2[i], q2[i], u2);
            }
        }
    }

    float* Fp = g_F + (((size_t)b * CH + c) * D_MODEL + d) * D_STATE + sub * SPL;
#pragma unroll
    for (int i = 0; i < PACKS; i += 2) {
        float4 v;
        unpack2(q2[i],   v.x, v.y);
        unpack2(q2[i+1], v.z, v.w);
        *reinterpret_cast<float4*>(Fp + 2 * i) = v;
    }
}

// ---------------- Middle: chain Qin across chunks ---------------------------
__global__ void __launch_bounds__(256)
mid_kernel()
{
    int idx = blockIdx.x * 256 + threadIdx.x;
    int dn  = idx & (D_MODEL * D_STATE - 1);
    int b   = idx >> 14;

    float aP = g_aP[dn];
    float q  = g_q0[dn];
    size_t stride = (size_t)D_MODEL * D_STATE;
    float* Qp = g_Qin + (size_t)b * CH * stride + dn;
    const float* Fp = g_F + (size_t)b * CH * stride + dn;

    Qp[0] = q;
#pragma unroll
    for (int c = 1; c < CH; c++) {
        q = fmaf(aP, q, Fp[(c - 1) * stride]);
        Qp[c * stride] = q;
    }
}

// ---------------- Pass 2: full scan per chunk -------------------------------
__global__ void __launch_bounds__(TPB, 7)
pass2_kernel(const float* __restrict__ u, float* __restrict__ y)
{
    __shared__ float tile[2][TS * DPB];

    int tid  = threadIdx.x;
    int pl   = tid >> 2;
    int sub  = tid & (LANES - 1);
    int sub1 = sub ^ 1, sub2 = sub ^ 2, sub3 = sub ^ 3;

    int blk  = blockIdx.x;
    int dblk = blk & 7;
    int bc   = blk >> 3;
    int c    = bc & (CH - 1);
    int b    = bc >> 4;
    int d    = dblk * DPB + pl;

    u64p a2[PACKS], cba2[PACKS], q2[PACKS];
    float S = 0.0f;
    int base = d * D_STATE + sub * SPL;
    const float* Qp = g_Qin + (((size_t)b * CH + c) * D_MODEL + d) * D_STATE + sub * SPL;
#pragma unroll
    for (int i = 0; i < PACKS; i += 2) {
        float4 av  = *reinterpret_cast<const float4*>(g_a  + base + 2 * i);
        float4 cbv = *reinterpret_cast<const float4*>(g_cb + base + 2 * i);
        float4 qv  = *reinterpret_cast<const float4*>(Qp + 2 * i);
        a2 [i]    = pack2(av.x,  av.y);   a2 [i+1]  = pack2(av.z,  av.w);
        cba2[i]   = pack2(cbv.x * av.x, cbv.y * av.y);
        cba2[i+1] = pack2(cbv.z * av.z, cbv.w * av.w);
        S += (cbv.x + cbv.y) + (cbv.z + cbv.w);
        q2 [i]    = pack2(qv.x,  qv.y);   q2 [i+1]  = pack2(qv.z,  qv.w);
    }

    const float* ubase = u + ((size_t)b * SEQ_LEN + (size_t)c * CLEN) * D_MODEL + dblk * DPB;
    float*       yp    = y + ((size_t)b * SEQ_LEN + (size_t)c * CLEN) * D_MODEL + d;

#pragma unroll
    for (int k = 0; k < 4; k++) {
        int s  = tid + k * TPB;
        int tl = s >> 3, c4 = (s & 7) * 4;
        cp16(smem_u32(&tile[0][tl * DPB + c4]), ubase + tl * D_MODEL + c4);
    }
    CP_COMMIT();

    // carried pair-sums: pS = pairSum(timestep sub), pS2 = pairSum(timestep sub^2)
    float pS = 0.0f, pS2 = 0.0f;

    for (int ct = 0; ct < NTILES; ct++) {
        CP_WAIT0();
        __syncthreads();
        if (ct + 1 < NTILES) {
            const float* src = ubase + (size_t)(ct + 1) * TS * D_MODEL;
            float* dst = tile[(ct + 1) & 1];
#pragma unroll
            for (int k = 0; k < 4; k++) {
                int s  = tid + k * TPB;
                int tl = s >> 3, c4 = (s & 7) * 4;
                cp16(smem_u32(&dst[tl * DPB + c4]), src + tl * D_MODEL + c4);
            }
            CP_COMMIT();
        }

        const float* tp = tile[ct & 1];
        float uv[2][4];
        float sA[4];

#pragma unroll
        for (int j = 0; j < 4; j++)
            uv[0][j] = tp[j * DPB + pl];

#pragma unroll
        for (int g = 0; g < TS / 4; g++) {
            int t0 = g * 4;
            float* uvC = uv[g & 1];
            float* uvN = uv[(g + 1) & 1];

            // (a) LDS next group (latency hidden by compute)
            if (g + 1 < TS / 4) {
#pragma unroll
                for (int j = 0; j < 4; j++)
                    uvN[j] = tp[(t0 + 4 + j) * DPB + pl];
            }

            // (b) compute steps 0,1
#pragma unroll
            for (int j = 0; j < 2; j++) {
                u64p u2 = pack2(uvC[j], uvC[j]);
                u64p e = mul2(cba2[0], q2[0]);
                u64p o = mul2(cba2[1], q2[1]);
                e = fma2(cba2[2], q2[2], e);
                o = fma2(cba2[3], q2[3], o);
                e = fma2(cba2[4], q2[4], e);
                o = fma2(cba2[5], q2[5], o);
                e = fma2(cba2[6], q2[6], e);
                o = fma2(cba2[7], q2[7], o);
#pragma unroll
                for (int i = 0; i < PACKS; i++)
                    q2[i] = fma2(a2[i], q2[i], u2);
                u64p t = add2(e, o);
                float lo, hi;
                unpack2(t, lo, hi);
                sA[j] = fmaf(S, uvC[j], lo + hi);
            }

            // (c) deferred stage-2 for previous group: 1 shfl.
            //     Partner (lane^2) sends its pairSum(sub^2) == our timestep sub.
            {
                float r2  = __shfl_xor_sync(0xffffffffu, pS2, 2);
                float fin = pS + r2;
                if (ct > 0 || g > 0) {
                    int tpos = (g == 0) ? (ct * TS - 4) : (ct * TS + t0 - 4);
                    __stcs(yp + (tpos + sub) * D_MODEL, fin);
                }
            }

            // (d) compute steps 2,3
#pragma unroll
            for (int j = 2; j < 4; j++) {
                u64p u2 = pack2(uvC[j], uvC[j]);
                u64p e = mul2(cba2[0], q2[0]);
                u64p o = mul2(cba2[1], q2[1]);
                e = fma2(cba2[2], q2[2], e);
                o = fma2(cba2[3], q2[3], o);
                e = fma2(cba2[4], q2[4], e);
                o = fma2(cba2[5], q2[5], o);
                e = fma2(cba2[6], q2[6], e);
                o = fma2(cba2[7], q2[7], o);
#pragma unroll
                for (int i = 0; i < PACKS; i++)
                    q2[i] = fma2(a2[i], q2[i], u2);
                u64p t = add2(e, o);
                float lo, hi;
                unpack2(t, lo, hi);
                sA[j] = fmaf(S, uvC[j], lo + hi);
            }

            // (e) stage-1: 2 shfls.  send sA[sub^1] over xor-1 -> recv sA[sub];
            //     send sA[sub^3] over xor-1 -> recv sA[sub^2].
            {
                float s1 = sel4(sA[0], sA[1], sA[2], sA[3], sub1);
                float s3 = sel4(sA[0], sA[1], sA[2], sA[3], sub3);
                float r1 = __shfl_xor_sync(0xffffffffu, s1, 1);
                float r3 = __shfl_xor_sync(0xffffffffu, s3, 1);
                float pA = sel4(sA[0], sA[1], sA[2], sA[3], sub);
                float pC = sel4(sA[0], sA[1], sA[2], sA[3], sub2);
                pS  = pA + r1;      // pairSum(timestep sub)   over {l, l^1}
                pS2 = pC + r3;      // pairSum(timestep sub^2) over {l, l^1}
            }
        }
    }

    // epilogue: stage-2 + store for the final group of the last tile
    {
        float r2  = __shfl_xor_sync(0xffffffffu, pS2, 2);
        float fin = pS + r2;
        __stcs(yp + (CLEN - 4 + sub) * D_MODEL, fin);
    }
}

extern "C" void kernel_launch(void* const* d_in, const int* in_sizes, int n_in,
                              void* d_out, int out_size)
{
    const float* u      = (const float*)d_in[0];
    const float* log_dt = (const float*)d_in[1];
    const float* A_real = (const float*)d_in[2];
    const float* B      = (const float*)d_in[3];
    const float* C      = (const float*)d_in[4];
    const float* x0     = (const float*)d_in[5];
    float* y = (float*)d_out;

    precomp_kernel<<<(D_MODEL * D_STATE + 255) / 256, 256>>>(log_dt, A_real, B, C, x0);

    int p1_blocks = BATCH * (CH - 1) * (D_MODEL / DPB);    // 3840
    pass1_kernel<<<p1_blocks, TPB>>>(u);

    int mid_threads = BATCH * D_MODEL * D_STATE;           // 524288
    mid_kernel<<<mid_threads / 256, 256>>>();

    int p2_blocks = BATCH * CH * (D_MODEL / DPB);          // 4096
    pass2_kernel<<<p2_blocks, TPB>>>(u, y);
}